// round 1
// baseline (speedup 1.0000x reference)
#include <cuda_runtime.h>
#include <cuda_bf16.h>

#define NMAX 100000
#define EMAX 1600000
#define MASKV (-1000000000.0f)
#define INV_TAU 2.0f

// ---------------- device scratch (static allocation only) ----------------
struct Scr {
    float poolsum[128];
    unsigned int poolmax[128];
    float pool[256];
    unsigned long long best[2];
    float zmax[2];
    float S[2];
    int isel[2];
};

__device__ float d_H [NMAX * 128];
__device__ float d_XA[NMAX * 128];
__device__ float d_XB[NMAX * 128];
__device__ int   d_counts[NMAX];
__device__ int   d_rowstart[NMAX + 1];
__device__ int   d_cursor[NMAX];
__device__ int   d_csr[EMAX];
__device__ float d_dinv[NMAX];
__device__ float d_z1[NMAX];
__device__ float d_l2[NMAX];
__device__ float d_z2[NMAX];
__device__ unsigned char d_conn[NMAX];
__device__ Scr   d_scr;

// ---------------- CSR build ----------------
__global__ void degcount_k(const int* __restrict__ dstp, int E) {
    int e = blockIdx.x * blockDim.x + threadIdx.x;
    if (e < E) atomicAdd(&d_counts[dstp[e]], 1);
}

// single-block scan over counts -> rowstart (exclusive), cursor copy, dinv
__global__ void scan_csr_k(int n) {
    __shared__ int part[1024];
    int t = threadIdx.x;
    int CH = (n + 1023) / 1024;
    int beg = t * CH;
    int end = beg + CH; if (end > n) end = n;
    int s = 0;
    for (int i = beg; i < end; i++) s += d_counts[i];
    part[t] = s;
    __syncthreads();
    for (int d = 1; d < 1024; d <<= 1) {
        int add = (t >= d) ? part[t - d] : 0;
        __syncthreads();
        part[t] += add;
        __syncthreads();
    }
    int off = part[t] - s;  // exclusive prefix
    for (int i = beg; i < end; i++) {
        int c = d_counts[i];
        d_rowstart[i] = off;
        d_cursor[i]   = off;
        d_dinv[i]     = rsqrtf((float)c + 1.0f);
        off += c;
    }
    if (t == 0) d_rowstart[n] = part[1023];
}

__global__ void fill_csr_k(const int* __restrict__ srcp, const int* __restrict__ dstp, int E) {
    int e = blockIdx.x * blockDim.x + threadIdx.x;
    if (e < E) {
        int d = dstp[e];
        int pos = atomicAdd(&d_cursor[d], 1);
        d_csr[pos] = srcp[e];
    }
}

// ---------------- dense GEMM: H = X @ W (X [n,128], W [128,128]) ----------------
__global__ __launch_bounds__(256) void gemm128_k(const float* __restrict__ X,
                                                 const float* __restrict__ W,
                                                 float* __restrict__ Hout, int n) {
    extern __shared__ float sh[];
    float* ws = sh;              // 128*128
    float* xs = sh + 128 * 128;  // 64*128
    int t = threadIdx.x;
    for (int i = t; i < 128 * 128; i += 256) ws[i] = W[i];
    int row0 = blockIdx.x * 64;
    int nr = n - row0; if (nr > 64) nr = 64;
    for (int i = t; i < nr * 128; i += 256) xs[i] = X[(size_t)row0 * 128 + i];
    __syncthreads();

    int tx = t & 31;   // col group: cols tx*4 .. tx*4+3
    int ty = t >> 5;   // row group: rows ty, ty+8, ... (whole warp shares ty -> LDS broadcast)
    float acc[8][4];
#pragma unroll
    for (int i = 0; i < 8; i++) { acc[i][0]=0.f; acc[i][1]=0.f; acc[i][2]=0.f; acc[i][3]=0.f; }

#pragma unroll 4
    for (int k = 0; k < 128; k++) {
        float4 w4 = *(const float4*)(ws + k * 128 + tx * 4);
#pragma unroll
        for (int i = 0; i < 8; i++) {
            float xv = xs[(ty + 8 * i) * 128 + k];
            acc[i][0] += xv * w4.x;
            acc[i][1] += xv * w4.y;
            acc[i][2] += xv * w4.z;
            acc[i][3] += xv * w4.w;
        }
    }
#pragma unroll
    for (int i = 0; i < 8; i++) {
        int r = ty + 8 * i;
        if (r < nr) {
            float4 o; o.x = acc[i][0]; o.y = acc[i][1]; o.z = acc[i][2]; o.w = acc[i][3];
            *(float4*)(Hout + (size_t)(row0 + r) * 128 + tx * 4) = o;
        }
    }
}

// ---------------- aggregation: out_i = relu(dinv_i * sum_{e:dst=i} H[src]*dinv[src]
//                                           + H[i]*dinv_i^2 + b) ----------------
__global__ __launch_bounds__(256) void aggregate_k(const float* __restrict__ H,
                                                   const float* __restrict__ bias,
                                                   float* __restrict__ outp, int n) {
    int w = (blockIdx.x * blockDim.x + threadIdx.x) >> 5;
    int lane = threadIdx.x & 31;
    if (w >= n) return;
    int beg = d_rowstart[w];
    int end = d_rowstart[w + 1];
    float ax = 0.f, ay = 0.f, az = 0.f, aw = 0.f;
    for (int e = beg; e < end; e++) {
        int s = d_csr[e];
        float c = d_dinv[s];
        float4 h4 = *(const float4*)(H + (size_t)s * 128 + lane * 4);
        ax += c * h4.x; ay += c * h4.y; az += c * h4.z; aw += c * h4.w;
    }
    float di = d_dinv[w];
    float4 hs = *(const float4*)(H + (size_t)w * 128 + lane * 4);
    float4 b4 = *(const float4*)(bias + lane * 4);
    float sc = di * di;
    float4 o;
    o.x = fmaxf(di * ax + sc * hs.x + b4.x, 0.f);
    o.y = fmaxf(di * ay + sc * hs.y + b4.y, 0.f);
    o.z = fmaxf(di * az + sc * hs.z + b4.z, 0.f);
    o.w = fmaxf(di * aw + sc * hs.w + b4.w, 0.f);
    *(float4*)(outp + (size_t)w * 128 + lane * 4) = o;
}

// ---------------- pooling ----------------
__global__ void pool_reduce_k(const float* __restrict__ G, int n) {
    int t = threadIdx.x;  // 128
    float s = 0.f, m = 0.f;  // relu outputs are >= 0
    for (int r = blockIdx.x; r < n; r += gridDim.x) {
        float v = G[(size_t)r * 128 + t];
        s += v;
        m = fmaxf(m, v);
    }
    atomicAdd(&d_scr.poolsum[t], s);
    atomicMax(&d_scr.poolmax[t], __float_as_uint(m));  // valid for nonneg floats
}

__global__ void pool_final_k(int n) {
    int t = threadIdx.x;  // 256
    if (t < 128) d_scr.pool[t] = d_scr.poolsum[t] / (float)n;
    else         d_scr.pool[t] = __uint_as_float(d_scr.poolmax[t - 128]);
}

// ---------------- head GEMVs: z1 = (pool@n1W + n1b + g1)/tau ; l2 = pool@n2W + n2b ----
__global__ __launch_bounds__(256) void gemv_heads_k(const float* __restrict__ n1W,
                                                    const float* __restrict__ n1b,
                                                    const float* __restrict__ g1,
                                                    const float* __restrict__ n2W,
                                                    const float* __restrict__ n2b,
                                                    int ncols, int halfblocks) {
    __shared__ float p[256];
    int t = threadIdx.x;
    p[t] = d_scr.pool[t];
    __syncthreads();
    int second = blockIdx.x >= halfblocks;
    int b = second ? blockIdx.x - halfblocks : blockIdx.x;
    int j4 = b * blockDim.x + t;
    if (j4 * 4 >= ncols) return;
    const float* W = second ? n2W : n1W;
    float ax = 0.f, ay = 0.f, az = 0.f, aw = 0.f;
#pragma unroll 4
    for (int k = 0; k < 256; k++) {
        float4 w4 = *(const float4*)(W + (size_t)k * ncols + j4 * 4);
        float pv = p[k];
        ax += pv * w4.x; ay += pv * w4.y; az += pv * w4.z; aw += pv * w4.w;
    }
    int j = j4 * 4;
    if (!second) {
        float4 bb = *(const float4*)(n1b + j);
        float4 gg = *(const float4*)(g1 + j);
        float4 o;
        o.x = (ax + bb.x + gg.x) * INV_TAU;
        o.y = (ay + bb.y + gg.y) * INV_TAU;
        o.z = (az + bb.z + gg.z) * INV_TAU;
        o.w = (aw + bb.w + gg.w) * INV_TAU;
        *(float4*)(d_z1 + j) = o;
    } else {
        float4 bb = *(const float4*)(n2b + j);
        float4 o;
        o.x = ax + bb.x; o.y = ay + bb.y; o.z = az + bb.z; o.w = aw + bb.w;
        *(float4*)(d_l2 + j) = o;
    }
}

// ---------------- argmax (packed atomicMax; ties -> lowest index, matches jnp) ----
__device__ __forceinline__ unsigned enc_f(float f) {
    unsigned u = __float_as_uint(f);
    return (u & 0x80000000u) ? ~u : (u | 0x80000000u);
}

__global__ void argmax_k(const float* __restrict__ z, int n, int which) {
    __shared__ unsigned long long sm[256];
    int t = threadIdx.x;
    unsigned long long best = 0ull;
    for (int j = blockIdx.x * blockDim.x + t; j < n; j += gridDim.x * blockDim.x) {
        unsigned long long key = ((unsigned long long)enc_f(z[j]) << 32)
                               | (unsigned long long)(0xFFFFFFFFu - (unsigned)j);
        if (key > best) best = key;
    }
    sm[t] = best;
    __syncthreads();
    for (int s = 128; s > 0; s >>= 1) {
        if (t < s && sm[t + s] > sm[t]) sm[t] = sm[t + s];
        __syncthreads();
    }
    if (t == 0) atomicMax(&d_scr.best[which], sm[0]);
}

__global__ void decode_k(int which) {
    unsigned long long b = d_scr.best[which];
    unsigned u = (unsigned)(b >> 32);
    unsigned bits = (u & 0x80000000u) ? (u & 0x7FFFFFFFu) : ~u;
    int idx = (int)(0xFFFFFFFFu - (unsigned)(b & 0xFFFFFFFFull));
    d_scr.isel[which] = idx;
    d_scr.zmax[which] = __uint_as_float(bits);
    if (which == 0) d_conn[idx] = 1;
}

// ---------------- mask of nodes connected to i1 ----------------
__global__ void conn_k(const int* __restrict__ srcp, const int* __restrict__ dstp, int E) {
    int i1 = d_scr.isel[0];
    int e = blockIdx.x * blockDim.x + threadIdx.x;
    if (e < E) {
        int s = srcp[e], d = dstp[e];
        if (s == i1 || d == i1) { d_conn[s] = 1; d_conn[d] = 1; }
    }
}

__global__ void z2_k(const float* __restrict__ g2, int n) {
    int j = blockIdx.x * blockDim.x + threadIdx.x;
    if (j < n) {
        float l = d_conn[j] ? MASKV : d_l2[j];
        d_z2[j] = (l + g2[j]) * INV_TAU;
    }
}

// ---------------- softmax (exp + sum, then normalize) ----------------
__global__ void exp_k(const float* __restrict__ z, float* __restrict__ outp, int n, int which) {
    __shared__ float sm[256];
    int t = threadIdx.x;
    float zm = d_scr.zmax[which];
    float ls = 0.f;
    for (int j = blockIdx.x * blockDim.x + t; j < n; j += gridDim.x * blockDim.x) {
        float e = expf(z[j] - zm);
        outp[j] = e;
        ls += e;
    }
    sm[t] = ls;
    __syncthreads();
    for (int s = 128; s > 0; s >>= 1) {
        if (t < s) sm[t] += sm[t + s];
        __syncthreads();
    }
    if (t == 0) atomicAdd(&d_scr.S[which], sm[0]);
}

__global__ void norm_k(float* __restrict__ outp, int n, int which) {
    float inv = 1.0f / d_scr.S[which];
    int j = blockIdx.x * blockDim.x + threadIdx.x;
    if (j < n) outp[j] *= inv;
}

// ---------------- edge-type head + stop head ----------------
__global__ void esoft_k(const float* __restrict__ G, const float* __restrict__ eW,
                        const float* __restrict__ eb, const float* __restrict__ ge,
                        float* __restrict__ outp, int n) {
    __shared__ float red[3][128];
    int t = threadIdx.x;  // 128
    int i1 = d_scr.isel[0];
    int i2 = d_scr.isel[1];
    float a = G[(size_t)i1 * 128 + t];
    float b = G[(size_t)i2 * 128 + t];
#pragma unroll
    for (int o = 0; o < 3; o++)
        red[o][t] = a * eW[t * 3 + o] + b * eW[(128 + t) * 3 + o];
    __syncthreads();
    for (int s = 64; s > 0; s >>= 1) {
        if (t < s) {
            red[0][t] += red[0][t + s];
            red[1][t] += red[1][t + s];
            red[2][t] += red[2][t + s];
        }
        __syncthreads();
    }
    if (t == 0) {
        float z0 = (red[0][0] + eb[0] + ge[0]) * INV_TAU;
        float z1v = (red[1][0] + eb[1] + ge[1]) * INV_TAU;
        float z2v = (red[2][0] + eb[2] + ge[2]) * INV_TAU;
        float m = fmaxf(z0, fmaxf(z1v, z2v));
        float e0 = expf(z0 - m), e1 = expf(z1v - m), e2 = expf(z2v - m);
        float inv = 1.0f / (e0 + e1 + e2);
        outp[2 * n + 0] = e0 * inv;
        outp[2 * n + 1] = e1 * inv;
        outp[2 * n + 2] = e2 * inv;
        outp[2 * n + 3] = 1.0f;  // softmax over a single logit == 1
    }
}

// ---------------- launcher ----------------
extern "C" void kernel_launch(void* const* d_in, const int* in_sizes, int n_in,
                              void* d_out, int out_size) {
    const float* x   = (const float*)d_in[0];
    const int*   ei  = (const int*)  d_in[1];
    const float* W1  = (const float*)d_in[2];
    const float* b1  = (const float*)d_in[3];
    const float* W2  = (const float*)d_in[4];
    const float* b2  = (const float*)d_in[5];
    const float* W3  = (const float*)d_in[6];
    const float* b3  = (const float*)d_in[7];
    const float* n1W = (const float*)d_in[8];
    const float* n1b = (const float*)d_in[9];
    const float* n2W = (const float*)d_in[10];
    const float* n2b = (const float*)d_in[11];
    const float* eW  = (const float*)d_in[12];
    const float* eb  = (const float*)d_in[13];
    const float* g1  = (const float*)d_in[16];
    const float* g2  = (const float*)d_in[17];
    const float* ge  = (const float*)d_in[18];
    float* out = (float*)d_out;

    int n = in_sizes[0] / 128;
    int E = in_sizes[1] / 2;
    const int* srcp = ei;
    const int* dstp = ei + E;

    void *pc, *pconn, *pscr, *pH, *pXA, *pXB;
    cudaGetSymbolAddress(&pc,   d_counts);
    cudaGetSymbolAddress(&pconn, d_conn);
    cudaGetSymbolAddress(&pscr, d_scr);
    cudaGetSymbolAddress(&pH,   d_H);
    cudaGetSymbolAddress(&pXA,  d_XA);
    cudaGetSymbolAddress(&pXB,  d_XB);
    float* H  = (float*)pH;
    float* XA = (float*)pXA;
    float* XB = (float*)pXB;

    cudaFuncSetAttribute(gemm128_k, cudaFuncAttributeMaxDynamicSharedMemorySize, 98304);

    cudaMemsetAsync(pc,   0, (size_t)n * sizeof(int), 0);
    cudaMemsetAsync(pconn, 0, (size_t)n, 0);
    cudaMemsetAsync(pscr, 0, sizeof(Scr), 0);

    int eblocks = (E + 255) / 256;
    degcount_k<<<eblocks, 256>>>(dstp, E);
    scan_csr_k<<<1, 1024>>>(n);
    fill_csr_k<<<eblocks, 256>>>(srcp, dstp, E);

    int gblocks = (n + 63) / 64;
    int ablocks = (n + 7) / 8;  // warp per node, 8 warps/block

    gemm128_k<<<gblocks, 256, 98304>>>(x,  W1, H, n);
    aggregate_k<<<ablocks, 256>>>(H, b1, XA, n);
    gemm128_k<<<gblocks, 256, 98304>>>(XA, W2, H, n);
    aggregate_k<<<ablocks, 256>>>(H, b2, XB, n);
    gemm128_k<<<gblocks, 256, 98304>>>(XB, W3, H, n);
    aggregate_k<<<ablocks, 256>>>(H, b3, XA, n);  // XA = gcn

    pool_reduce_k<<<512, 128>>>(XA, n);
    pool_final_k<<<1, 256>>>(n);

    int halfblocks = (n / 4 + 255) / 256;
    gemv_heads_k<<<2 * halfblocks, 256>>>(n1W, n1b, g1, n2W, n2b, n, halfblocks);

    argmax_k<<<128, 256>>>((const float*)0 + 0, 0, 0);  // placeholder removed below
    // NOTE: real calls follow; the above line is never what we want -- replaced:

    // n1 head
    {
        void* pz1; cudaGetSymbolAddress(&pz1, d_z1);
        void* pz2; cudaGetSymbolAddress(&pz2, d_z2);
        const float* z1p = (const float*)pz1;
        const float* z2p = (const float*)pz2;

        // overwrite placeholder effect: run the proper reduction (placeholder had n=0, no-op)
        argmax_k<<<128, 256>>>(z1p, n, 0);
        decode_k<<<1, 1>>>(0);
        conn_k<<<eblocks, 256>>>(srcp, dstp, E);
        exp_k<<<256, 256>>>(z1p, out, n, 0);
        norm_k<<<(n + 255) / 256, 256>>>(out, n, 0);

        z2_k<<<(n + 255) / 256, 256>>>(g2, n);
        argmax_k<<<128, 256>>>(z2p, n, 1);
        decode_k<<<1, 1>>>(1);
        exp_k<<<256, 256>>>(z2p, out + n, n, 1);
        norm_k<<<(n + 255) / 256, 256>>>(out + n, n, 1);
    }

    esoft_k<<<1, 128>>>(XA, eW, eb, ge, out, n);
}

// round 2
// speedup vs baseline: 1.0409x; 1.0409x over previous
#include <cuda_runtime.h>
#include <cuda_bf16.h>

#define NMAX 100000
#define EMAX 1600000
#define MASKV (-1000000000.0f)
#define INV_TAU 2.0f

// ---------------- device scratch (static allocation only) ----------------
struct Scr {
    float poolsum[128];
    unsigned int poolmax[128];
    float pool[256];
    unsigned long long best[2];
    float zmax[2];
    float S[2];
    int isel[2];
};

__device__ float d_H [NMAX * 128];
__device__ float d_XA[NMAX * 128];
__device__ float d_XB[NMAX * 128];
__device__ int   d_counts[NMAX];
__device__ int   d_rowstart[NMAX + 1];
__device__ int   d_cursor[NMAX];
__device__ int   d_csr[EMAX];
__device__ float d_dinv[NMAX];
__device__ float d_z1[NMAX];
__device__ float d_l2[NMAX];
__device__ float d_z2[NMAX];
__device__ unsigned char d_conn[NMAX];
__device__ Scr   d_scr;

// ---------------- CSR build ----------------
__global__ void degcount_k(const int* __restrict__ dstp, int E) {
    int e = blockIdx.x * blockDim.x + threadIdx.x;
    if (e < E) atomicAdd(&d_counts[dstp[e]], 1);
}

// single-block scan over counts -> rowstart (exclusive), cursor copy, dinv
__global__ void scan_csr_k(int n) {
    __shared__ int part[1024];
    int t = threadIdx.x;
    int CH = (n + 1023) / 1024;
    int beg = t * CH;
    int end = beg + CH; if (end > n) end = n;
    int s = 0;
#pragma unroll 4
    for (int i = beg; i < end; i++) s += d_counts[i];
    part[t] = s;
    __syncthreads();
    for (int d = 1; d < 1024; d <<= 1) {
        int add = (t >= d) ? part[t - d] : 0;
        __syncthreads();
        part[t] += add;
        __syncthreads();
    }
    int off = part[t] - s;  // exclusive prefix
    for (int i = beg; i < end; i++) {
        int c = d_counts[i];
        d_rowstart[i] = off;
        d_cursor[i]   = off;
        d_dinv[i]     = rsqrtf((float)c + 1.0f);
        off += c;
    }
    if (t == 0) d_rowstart[n] = part[1023];
}

__global__ void fill_csr_k(const int* __restrict__ srcp, const int* __restrict__ dstp, int E) {
    int e = blockIdx.x * blockDim.x + threadIdx.x;
    if (e < E) {
        int d = dstp[e];
        int pos = atomicAdd(&d_cursor[d], 1);
        d_csr[pos] = srcp[e];
    }
}

// ---------------- 3xTF32 tensor-core GEMM: H = X @ W ----------------
// X [n,128] row-major, W [128,128] row-major (k,n). Block: 64 rows x 128 cols.
#define XS_STRIDE 132
#define WS_STRIDE 136

__device__ __forceinline__ unsigned f2tf32(float f) {
    unsigned r;
    asm("cvt.rna.tf32.f32 %0, %1;" : "=r"(r) : "f"(f));
    return r;
}

__device__ __forceinline__ void mma_tf32(float* d,
                                         unsigned a0, unsigned a1, unsigned a2, unsigned a3,
                                         unsigned b0, unsigned b1) {
    asm volatile("mma.sync.aligned.m16n8k8.row.col.f32.tf32.tf32.f32 "
                 "{%0,%1,%2,%3}, {%4,%5,%6,%7}, {%8,%9}, {%0,%1,%2,%3};"
                 : "+f"(d[0]), "+f"(d[1]), "+f"(d[2]), "+f"(d[3])
                 : "r"(a0), "r"(a1), "r"(a2), "r"(a3), "r"(b0), "r"(b1));
}

__global__ __launch_bounds__(256) void gemm_tf32_k(const float* __restrict__ X,
                                                   const float* __restrict__ W,
                                                   float* __restrict__ Hout, int n) {
    extern __shared__ float sh[];
    float* xs = sh;                      // 64 x XS_STRIDE
    float* ws = sh + 64 * XS_STRIDE;     // 128 x WS_STRIDE
    int t = threadIdx.x;
    int row0 = blockIdx.x * 64;
    int nr = n - row0; if (nr > 64) nr = 64;

    // load W tile (full 128x128)
    for (int i = t; i < 128 * 32; i += 256) {
        int k = i >> 5;
        int c4 = i & 31;
        float4 v = *(const float4*)(W + k * 128 + c4 * 4);
        *(float4*)(ws + k * WS_STRIDE + c4 * 4) = v;
    }
    // load X tile (zero-pad tail block)
    if (nr < 64) {
        for (int i = t; i < 64 * XS_STRIDE; i += 256) xs[i] = 0.f;
        __syncthreads();
    }
    for (int i = t; i < nr * 32; i += 256) {
        int r = i >> 5;
        int c4 = i & 31;
        float4 v = *(const float4*)(X + (size_t)(row0 + r) * 128 + c4 * 4);
        *(float4*)(xs + r * XS_STRIDE + c4 * 4) = v;
    }
    __syncthreads();

    int lane = t & 31, wid = t >> 5;
    int wm = wid & 3, wn = wid >> 2;     // warp tile: rows wm*16.., cols wn*64..
    int m0 = wm * 16, n0 = wn * 64;
    int r = lane >> 2, c = lane & 3;

    float acc[8][4];
#pragma unroll
    for (int j = 0; j < 8; j++) { acc[j][0]=0.f; acc[j][1]=0.f; acc[j][2]=0.f; acc[j][3]=0.f; }

    const float* xb = xs + (m0 + r) * XS_STRIDE + c;
    for (int kk = 0; kk < 128; kk += 8) {
        float a0f = xb[kk];
        float a1f = xb[kk + 8 * XS_STRIDE];
        float a2f = xb[kk + 4];
        float a3f = xb[kk + 8 * XS_STRIDE + 4];
        unsigned ah0 = f2tf32(a0f), ah1 = f2tf32(a1f), ah2 = f2tf32(a2f), ah3 = f2tf32(a3f);
        unsigned al0 = f2tf32(a0f - __uint_as_float(ah0));
        unsigned al1 = f2tf32(a1f - __uint_as_float(ah1));
        unsigned al2 = f2tf32(a2f - __uint_as_float(ah2));
        unsigned al3 = f2tf32(a3f - __uint_as_float(ah3));
        const float* wb = ws + (kk + c) * WS_STRIDE + n0 + r;
#pragma unroll
        for (int j = 0; j < 8; j++) {
            float b0f = wb[8 * j];
            float b1f = wb[4 * WS_STRIDE + 8 * j];
            unsigned bh0 = f2tf32(b0f), bh1 = f2tf32(b1f);
            unsigned bl0 = f2tf32(b0f - __uint_as_float(bh0));
            unsigned bl1 = f2tf32(b1f - __uint_as_float(bh1));
            mma_tf32(acc[j], ah0, ah1, ah2, ah3, bh0, bh1);
            mma_tf32(acc[j], al0, al1, al2, al3, bh0, bh1);
            mma_tf32(acc[j], ah0, ah1, ah2, ah3, bl0, bl1);
        }
    }

#pragma unroll
    for (int j = 0; j < 8; j++) {
        int col = n0 + 8 * j + 2 * c;
        int rr = row0 + m0 + r;
        if (m0 + r < nr)
            *(float2*)(Hout + (size_t)rr * 128 + col) = make_float2(acc[j][0], acc[j][1]);
        if (m0 + r + 8 < nr)
            *(float2*)(Hout + (size_t)(rr + 8) * 128 + col) = make_float2(acc[j][2], acc[j][3]);
    }
}

// ---------------- aggregation: out_i = relu(dinv_i * sum_{e:dst=i} H[src]*dinv[src]
//                                           + H[i]*dinv_i^2 + b) ----------------
__global__ __launch_bounds__(256) void aggregate_k(const float* __restrict__ H,
                                                   const float* __restrict__ bias,
                                                   float* __restrict__ outp, int n) {
    int w = (blockIdx.x * blockDim.x + threadIdx.x) >> 5;
    int lane = threadIdx.x & 31;
    if (w >= n) return;
    int beg = d_rowstart[w];
    int end = d_rowstart[w + 1];
    float ax = 0.f, ay = 0.f, az = 0.f, aw = 0.f;
    for (int base = beg; base < end; base += 32) {
        int rem = end - base;
        int idx = 0; float cc = 0.f;
        if (lane < rem) { idx = d_csr[base + lane]; cc = d_dinv[idx]; }
        int cnt = rem < 32 ? rem : 32;
        for (int j = 0; j < cnt; j++) {
            int s = __shfl_sync(0xffffffffu, idx, j);
            float cj = __shfl_sync(0xffffffffu, cc, j);
            float4 h4 = *(const float4*)(H + (size_t)s * 128 + lane * 4);
            ax = fmaf(cj, h4.x, ax);
            ay = fmaf(cj, h4.y, ay);
            az = fmaf(cj, h4.z, az);
            aw = fmaf(cj, h4.w, aw);
        }
    }
    float di = d_dinv[w];
    float4 hs = *(const float4*)(H + (size_t)w * 128 + lane * 4);
    float4 b4 = *(const float4*)(bias + lane * 4);
    float sc = di * di;
    float4 o;
    o.x = fmaxf(di * ax + sc * hs.x + b4.x, 0.f);
    o.y = fmaxf(di * ay + sc * hs.y + b4.y, 0.f);
    o.z = fmaxf(di * az + sc * hs.z + b4.z, 0.f);
    o.w = fmaxf(di * aw + sc * hs.w + b4.w, 0.f);
    *(float4*)(outp + (size_t)w * 128 + lane * 4) = o;
}

// ---------------- pooling ----------------
__global__ void pool_reduce_k(const float* __restrict__ G, int n) {
    int t = threadIdx.x;  // 128
    float s = 0.f, m = 0.f;  // relu outputs are >= 0
    for (int r = blockIdx.x; r < n; r += gridDim.x) {
        float v = G[(size_t)r * 128 + t];
        s += v;
        m = fmaxf(m, v);
    }
    atomicAdd(&d_scr.poolsum[t], s);
    atomicMax(&d_scr.poolmax[t], __float_as_uint(m));  // valid for nonneg floats
}

__global__ void pool_final_k(int n) {
    int t = threadIdx.x;  // 256
    if (t < 128) d_scr.pool[t] = d_scr.poolsum[t] / (float)n;
    else         d_scr.pool[t] = __uint_as_float(d_scr.poolmax[t - 128]);
}

// ---------------- argmax key helpers ----------------
__device__ __forceinline__ unsigned enc_f(float f) {
    unsigned u = __float_as_uint(f);
    return (u & 0x80000000u) ? ~u : (u | 0x80000000u);
}
__device__ __forceinline__ unsigned long long mkkey(float f, int j) {
    return ((unsigned long long)enc_f(f) << 32) | (unsigned long long)(0xFFFFFFFFu - (unsigned)j);
}

// ---------------- head GEMVs (z1 argmax fused) ----------------
__global__ __launch_bounds__(256) void gemv_heads_k(const float* __restrict__ n1W,
                                                    const float* __restrict__ n1b,
                                                    const float* __restrict__ g1,
                                                    const float* __restrict__ n2W,
                                                    const float* __restrict__ n2b,
                                                    int ncols, int halfblocks) {
    __shared__ float p[256];
    __shared__ unsigned long long redk[256];
    int t = threadIdx.x;
    p[t] = d_scr.pool[t];
    __syncthreads();
    int second = blockIdx.x >= halfblocks;
    int b = second ? blockIdx.x - halfblocks : blockIdx.x;
    int j4 = b * blockDim.x + t;
    bool valid = (j4 * 4 < ncols);
    float ax = 0.f, ay = 0.f, az = 0.f, aw = 0.f;
    if (valid) {
        const float* W = second ? n2W : n1W;
#pragma unroll 4
        for (int k = 0; k < 256; k++) {
            float4 w4 = *(const float4*)(W + (size_t)k * ncols + j4 * 4);
            float pv = p[k];
            ax += pv * w4.x; ay += pv * w4.y; az += pv * w4.z; aw += pv * w4.w;
        }
    }
    int j = j4 * 4;
    if (!second) {
        unsigned long long key = 0ull;
        if (valid) {
            float4 bb = *(const float4*)(n1b + j);
            float4 gg = *(const float4*)(g1 + j);
            float4 o;
            o.x = (ax + bb.x + gg.x) * INV_TAU;
            o.y = (ay + bb.y + gg.y) * INV_TAU;
            o.z = (az + bb.z + gg.z) * INV_TAU;
            o.w = (aw + bb.w + gg.w) * INV_TAU;
            *(float4*)(d_z1 + j) = o;
            key = mkkey(o.x, j);
            unsigned long long k1 = mkkey(o.y, j + 1); if (k1 > key) key = k1;
            unsigned long long k2 = mkkey(o.z, j + 2); if (k2 > key) key = k2;
            unsigned long long k3 = mkkey(o.w, j + 3); if (k3 > key) key = k3;
        }
        redk[t] = key;
        __syncthreads();
        for (int s = 128; s > 0; s >>= 1) {
            if (t < s && redk[t + s] > redk[t]) redk[t] = redk[t + s];
            __syncthreads();
        }
        if (t == 0) atomicMax(&d_scr.best[0], redk[0]);
    } else {
        if (valid) {
            float4 bb = *(const float4*)(n2b + j);
            float4 o;
            o.x = ax + bb.x; o.y = ay + bb.y; o.z = az + bb.z; o.w = aw + bb.w;
            *(float4*)(d_l2 + j) = o;
        }
    }
}

__global__ void decode_k(int which) {
    unsigned long long b = d_scr.best[which];
    unsigned u = (unsigned)(b >> 32);
    unsigned bits = (u & 0x80000000u) ? (u & 0x7FFFFFFFu) : ~u;
    int idx = (int)(0xFFFFFFFFu - (unsigned)(b & 0xFFFFFFFFull));
    d_scr.isel[which] = idx;
    d_scr.zmax[which] = __uint_as_float(bits);
    if (which == 0) d_conn[idx] = 1;
}

// ---------------- mask of nodes connected to i1 ----------------
__global__ void conn_k(const int* __restrict__ srcp, const int* __restrict__ dstp, int E) {
    int i1 = d_scr.isel[0];
    int e = blockIdx.x * blockDim.x + threadIdx.x;
    if (e < E) {
        int s = srcp[e], d = dstp[e];
        if (s == i1 || d == i1) { d_conn[s] = 1; d_conn[d] = 1; }
    }
}

// z2 compute + fused argmax
__global__ void z2argmax_k(const float* __restrict__ g2, int n) {
    __shared__ unsigned long long sm[256];
    int t = threadIdx.x;
    unsigned long long best = 0ull;
    for (int j = blockIdx.x * blockDim.x + t; j < n; j += gridDim.x * blockDim.x) {
        float l = d_conn[j] ? MASKV : d_l2[j];
        float z = (l + g2[j]) * INV_TAU;
        d_z2[j] = z;
        unsigned long long key = mkkey(z, j);
        if (key > best) best = key;
    }
    sm[t] = best;
    __syncthreads();
    for (int s = 128; s > 0; s >>= 1) {
        if (t < s && sm[t + s] > sm[t]) sm[t] = sm[t + s];
        __syncthreads();
    }
    if (t == 0) atomicMax(&d_scr.best[1], sm[0]);
}

// ---------------- softmax (exp + sum, then normalize) ----------------
__global__ void exp_k(const float* __restrict__ z, float* __restrict__ outp, int n, int which) {
    __shared__ float sm[256];
    int t = threadIdx.x;
    float zm = d_scr.zmax[which];
    float ls = 0.f;
    for (int j = blockIdx.x * blockDim.x + t; j < n; j += gridDim.x * blockDim.x) {
        float e = expf(z[j] - zm);
        outp[j] = e;
        ls += e;
    }
    sm[t] = ls;
    __syncthreads();
    for (int s = 128; s > 0; s >>= 1) {
        if (t < s) sm[t] += sm[t + s];
        __syncthreads();
    }
    if (t == 0) atomicAdd(&d_scr.S[which], sm[0]);
}

__global__ void norm_k(float* __restrict__ outp, int n, int which) {
    float inv = 1.0f / d_scr.S[which];
    int j = blockIdx.x * blockDim.x + threadIdx.x;
    if (j < n) outp[j] *= inv;
}

// ---------------- edge-type head + stop head ----------------
__global__ void esoft_k(const float* __restrict__ G, const float* __restrict__ eW,
                        const float* __restrict__ eb, const float* __restrict__ ge,
                        float* __restrict__ outp, int n) {
    __shared__ float red[3][128];
    int t = threadIdx.x;  // 128
    int i1 = d_scr.isel[0];
    int i2 = d_scr.isel[1];
    float a = G[(size_t)i1 * 128 + t];
    float b = G[(size_t)i2 * 128 + t];
#pragma unroll
    for (int o = 0; o < 3; o++)
        red[o][t] = a * eW[t * 3 + o] + b * eW[(128 + t) * 3 + o];
    __syncthreads();
    for (int s = 64; s > 0; s >>= 1) {
        if (t < s) {
            red[0][t] += red[0][t + s];
            red[1][t] += red[1][t + s];
            red[2][t] += red[2][t + s];
        }
        __syncthreads();
    }
    if (t == 0) {
        float z0 = (red[0][0] + eb[0] + ge[0]) * INV_TAU;
        float z1v = (red[1][0] + eb[1] + ge[1]) * INV_TAU;
        float z2v = (red[2][0] + eb[2] + ge[2]) * INV_TAU;
        float m = fmaxf(z0, fmaxf(z1v, z2v));
        float e0 = expf(z0 - m), e1 = expf(z1v - m), e2 = expf(z2v - m);
        float inv = 1.0f / (e0 + e1 + e2);
        outp[2 * n + 0] = e0 * inv;
        outp[2 * n + 1] = e1 * inv;
        outp[2 * n + 2] = e2 * inv;
        outp[2 * n + 3] = 1.0f;  // softmax over a single logit == 1
    }
}

// ---------------- launcher ----------------
extern "C" void kernel_launch(void* const* d_in, const int* in_sizes, int n_in,
                              void* d_out, int out_size) {
    const float* x   = (const float*)d_in[0];
    const int*   ei  = (const int*)  d_in[1];
    const float* W1  = (const float*)d_in[2];
    const float* b1  = (const float*)d_in[3];
    const float* W2  = (const float*)d_in[4];
    const float* b2  = (const float*)d_in[5];
    const float* W3  = (const float*)d_in[6];
    const float* b3  = (const float*)d_in[7];
    const float* n1W = (const float*)d_in[8];
    const float* n1b = (const float*)d_in[9];
    const float* n2W = (const float*)d_in[10];
    const float* n2b = (const float*)d_in[11];
    const float* eW  = (const float*)d_in[12];
    const float* eb  = (const float*)d_in[13];
    const float* g1  = (const float*)d_in[16];
    const float* g2  = (const float*)d_in[17];
    const float* ge  = (const float*)d_in[18];
    float* out = (float*)d_out;

    int n = in_sizes[0] / 128;
    int E = in_sizes[1] / 2;
    const int* srcp = ei;
    const int* dstp = ei + E;

    void *pc, *pconn, *pscr, *pH, *pXA, *pXB, *pz1, *pz2;
    cudaGetSymbolAddress(&pc,    d_counts);
    cudaGetSymbolAddress(&pconn, d_conn);
    cudaGetSymbolAddress(&pscr,  d_scr);
    cudaGetSymbolAddress(&pH,    d_H);
    cudaGetSymbolAddress(&pXA,   d_XA);
    cudaGetSymbolAddress(&pXB,   d_XB);
    cudaGetSymbolAddress(&pz1,   d_z1);
    cudaGetSymbolAddress(&pz2,   d_z2);
    float* H  = (float*)pH;
    float* XA = (float*)pXA;
    float* XB = (float*)pXB;
    const float* z1p = (const float*)pz1;
    const float* z2p = (const float*)pz2;

    const int GEMM_SMEM = (64 * XS_STRIDE + 128 * WS_STRIDE) * 4;  // 103424 B
    cudaFuncSetAttribute(gemm_tf32_k, cudaFuncAttributeMaxDynamicSharedMemorySize, GEMM_SMEM);

    cudaMemsetAsync(pc,    0, (size_t)n * sizeof(int), 0);
    cudaMemsetAsync(pconn, 0, (size_t)n, 0);
    cudaMemsetAsync(pscr,  0, sizeof(Scr), 0);

    int eblocks = (E + 255) / 256;
    degcount_k<<<eblocks, 256>>>(dstp, E);
    scan_csr_k<<<1, 1024>>>(n);
    fill_csr_k<<<eblocks, 256>>>(srcp, dstp, E);

    int gblocks = (n + 63) / 64;
    int ablocks = (n + 7) / 8;  // warp per node, 8 warps/block

    gemm_tf32_k<<<gblocks, 256, GEMM_SMEM>>>(x,  W1, H, n);
    aggregate_k<<<ablocks, 256>>>(H, b1, XA, n);
    gemm_tf32_k<<<gblocks, 256, GEMM_SMEM>>>(XA, W2, H, n);
    aggregate_k<<<ablocks, 256>>>(H, b2, XB, n);
    gemm_tf32_k<<<gblocks, 256, GEMM_SMEM>>>(XB, W3, H, n);
    aggregate_k<<<ablocks, 256>>>(H, b3, XA, n);  // XA = gcn

    pool_reduce_k<<<512, 128>>>(XA, n);
    pool_final_k<<<1, 256>>>(n);

    int halfblocks = (n / 4 + 255) / 256;
    gemv_heads_k<<<2 * halfblocks, 256>>>(n1W, n1b, g1, n2W, n2b, n, halfblocks);

    decode_k<<<1, 1>>>(0);
    conn_k<<<eblocks, 256>>>(srcp, dstp, E);
    exp_k<<<256, 256>>>(z1p, out, n, 0);
    norm_k<<<(n + 255) / 256, 256>>>(out, n, 0);

    z2argmax_k<<<256, 256>>>(g2, n);
    decode_k<<<1, 1>>>(1);
    exp_k<<<256, 256>>>(z2p, out + n, n, 1);
    norm_k<<<(n + 255) / 256, 256>>>(out + n, n, 1);

    esoft_k<<<1, 128>>>(XA, eW, eb, ge, out, n);
}

// round 3
// speedup vs baseline: 1.1597x; 1.1141x over previous
#include <cuda_runtime.h>
#include <cuda_bf16.h>

#define NMAX 100000
#define EMAX 1600000
#define MASKV (-1000000000.0f)
#define INV_TAU 2.0f

// ---------------- device scratch (static allocation only) ----------------
struct Scr {
    float poolsum[128];
    unsigned int poolmax[128];
    float pool[256];
    unsigned long long best[2];
    float zmax[2];
    float S[2];
    int isel[2];
};

__device__ float d_H [NMAX * 128];
__device__ float d_XA[NMAX * 128];
__device__ float d_XB[NMAX * 128];
__device__ int   d_counts[NMAX];
__device__ int   d_rowstart[NMAX + 1];
__device__ int   d_cursor[NMAX];
__device__ int   d_csr[EMAX];
__device__ float d_dinv[NMAX];
__device__ float d_z1[NMAX];
__device__ float d_l2[NMAX];
__device__ float d_z2[NMAX];
__device__ unsigned char d_conn[NMAX];
__device__ int   d_bsum[128];
__device__ int   d_boff[128];
__device__ Scr   d_scr;

// ---------------- CSR build ----------------
__global__ void degcount_k(const int* __restrict__ dstp, int E) {
    int e = blockIdx.x * blockDim.x + threadIdx.x;
    if (e < E) atomicAdd(&d_counts[dstp[e]], 1);
}

// 3-phase parallel scan: block sums -> scan of block sums -> per-block scan
__global__ void scan1_k(int n) {
    __shared__ int sm[1024];
    int t = threadIdx.x;
    int i = blockIdx.x * 1024 + t;
    int v = (i < n) ? d_counts[i] : 0;
    sm[t] = v;
    __syncthreads();
    for (int s = 512; s > 0; s >>= 1) {
        if (t < s) sm[t] += sm[t + s];
        __syncthreads();
    }
    if (t == 0) d_bsum[blockIdx.x] = sm[0];
}

__global__ void scan2_k(int nb, int n) {
    __shared__ int sm[128];
    int t = threadIdx.x;
    int v = (t < nb) ? d_bsum[t] : 0;
    sm[t] = v;
    __syncthreads();
    for (int d = 1; d < 128; d <<= 1) {
        int add = (t >= d) ? sm[t - d] : 0;
        __syncthreads();
        sm[t] += add;
        __syncthreads();
    }
    if (t < nb) d_boff[t] = sm[t] - v;
    if (t == nb - 1) d_rowstart[n] = sm[t];
}

__global__ void scan3_k(int n) {
    __shared__ int sm[1024];
    int t = threadIdx.x;
    int i = blockIdx.x * 1024 + t;
    int v = (i < n) ? d_counts[i] : 0;
    sm[t] = v;
    __syncthreads();
    for (int d = 1; d < 1024; d <<= 1) {
        int add = (t >= d) ? sm[t - d] : 0;
        __syncthreads();
        sm[t] += add;
        __syncthreads();
    }
    if (i < n) {
        int excl = sm[t] - v + d_boff[blockIdx.x];
        d_rowstart[i] = excl;
        d_cursor[i]   = excl;
        d_dinv[i]     = rsqrtf((float)v + 1.0f);
    }
}

__global__ void fill_csr_k(const int* __restrict__ srcp, const int* __restrict__ dstp, int E) {
    int e = blockIdx.x * blockDim.x + threadIdx.x;
    if (e < E) {
        int d = dstp[e];
        int pos = atomicAdd(&d_cursor[d], 1);
        d_csr[pos] = srcp[e];
    }
}

// ---------------- 3xTF32 tensor-core GEMM with smem-resident hi/lo split ----
// Computes Hout[i,:] = dinv[i] * (X @ W)[i,:]   (dinv pre-scaling fused)
// Block: 64 rows x 128 cols. K=128 in 2 chunks of 64.
#define XH_ST 68
#define WH_ST 136

__device__ __forceinline__ unsigned f2tf32(float f) {
    unsigned r;
    asm("cvt.rna.tf32.f32 %0, %1;" : "=r"(r) : "f"(f));
    return r;
}

__device__ __forceinline__ void mma_tf32(float* d,
                                         unsigned a0, unsigned a1, unsigned a2, unsigned a3,
                                         unsigned b0, unsigned b1) {
    asm volatile("mma.sync.aligned.m16n8k8.row.col.f32.tf32.tf32.f32 "
                 "{%0,%1,%2,%3}, {%4,%5,%6,%7}, {%8,%9}, {%0,%1,%2,%3};"
                 : "+f"(d[0]), "+f"(d[1]), "+f"(d[2]), "+f"(d[3])
                 : "r"(a0), "r"(a1), "r"(a2), "r"(a3), "r"(b0), "r"(b1));
}

__device__ __forceinline__ void split4(float4 v, float4& hi, float4& lo) {
    hi.x = __uint_as_float(f2tf32(v.x)); lo.x = __uint_as_float(f2tf32(v.x - hi.x));
    hi.y = __uint_as_float(f2tf32(v.y)); lo.y = __uint_as_float(f2tf32(v.y - hi.y));
    hi.z = __uint_as_float(f2tf32(v.z)); lo.z = __uint_as_float(f2tf32(v.z - hi.z));
    hi.w = __uint_as_float(f2tf32(v.w)); lo.w = __uint_as_float(f2tf32(v.w - hi.w));
}

__global__ __launch_bounds__(256) void gemm_tf32_k(const float* __restrict__ X,
                                                   const float* __restrict__ W,
                                                   float* __restrict__ Hout, int n) {
    extern __shared__ float sh[];
    float* xh = sh;                         // 64 x XH_ST
    float* xl = xh + 64 * XH_ST;
    float* wh = xl + 64 * XH_ST;            // 64 x WH_ST
    float* wl = wh + 64 * WH_ST;

    int t = threadIdx.x;
    int row0 = blockIdx.x * 64;
    int nr = n - row0; if (nr > 64) nr = 64;

    int lane = t & 31, wid = t >> 5;
    int wm = wid & 1, wn = wid >> 1;        // warp tile 32 rows x 32 cols
    int m0 = wm * 32, n0 = wn * 32;
    int r = lane >> 2, c = lane & 3;

    float acc[2][4][4];
#pragma unroll
    for (int mi = 0; mi < 2; mi++)
#pragma unroll
        for (int nj = 0; nj < 4; nj++)
#pragma unroll
            for (int q = 0; q < 4; q++) acc[mi][nj][q] = 0.f;

    for (int ch = 0; ch < 2; ch++) {
        if (ch) __syncthreads();
        // load W chunk: 64 k-rows x 128 cols, split hi/lo
        for (int i = t; i < 2048; i += 256) {
            int k = i >> 5;
            int c4 = i & 31;
            float4 v = *(const float4*)(W + (size_t)(ch * 64 + k) * 128 + c4 * 4);
            float4 hi, lo; split4(v, hi, lo);
            *(float4*)(wh + k * WH_ST + c4 * 4) = hi;
            *(float4*)(wl + k * WH_ST + c4 * 4) = lo;
        }
        // load X chunk: nr rows x 64 cols (garbage rows beyond nr only affect discarded outputs)
        for (int i = t; i < nr * 16; i += 256) {
            int rr = i >> 4;
            int c4 = i & 15;
            float4 v = *(const float4*)(X + (size_t)(row0 + rr) * 128 + ch * 64 + c4 * 4);
            float4 hi, lo; split4(v, hi, lo);
            *(float4*)(xh + rr * XH_ST + c4 * 4) = hi;
            *(float4*)(xl + rr * XH_ST + c4 * 4) = lo;
        }
        __syncthreads();

#pragma unroll
        for (int kk = 0; kk < 64; kk += 8) {
            unsigned ah[2][4], al[2][4];
#pragma unroll
            for (int mi = 0; mi < 2; mi++) {
                const float* xb  = xh + (m0 + mi * 16 + r) * XH_ST + c + kk;
                const float* xlb = xl + (m0 + mi * 16 + r) * XH_ST + c + kk;
                ah[mi][0] = __float_as_uint(xb[0]);
                ah[mi][1] = __float_as_uint(xb[8 * XH_ST]);
                ah[mi][2] = __float_as_uint(xb[4]);
                ah[mi][3] = __float_as_uint(xb[8 * XH_ST + 4]);
                al[mi][0] = __float_as_uint(xlb[0]);
                al[mi][1] = __float_as_uint(xlb[8 * XH_ST]);
                al[mi][2] = __float_as_uint(xlb[4]);
                al[mi][3] = __float_as_uint(xlb[8 * XH_ST + 4]);
            }
#pragma unroll
            for (int nj = 0; nj < 4; nj++) {
                const float* wb  = wh + (kk + c) * WH_ST + n0 + nj * 8 + r;
                const float* wlb = wl + (kk + c) * WH_ST + n0 + nj * 8 + r;
                unsigned bh0 = __float_as_uint(wb[0]);
                unsigned bh1 = __float_as_uint(wb[4 * WH_ST]);
                unsigned bl0 = __float_as_uint(wlb[0]);
                unsigned bl1 = __float_as_uint(wlb[4 * WH_ST]);
#pragma unroll
                for (int mi = 0; mi < 2; mi++) {
                    mma_tf32(acc[mi][nj], ah[mi][0], ah[mi][1], ah[mi][2], ah[mi][3], bh0, bh1);
                    mma_tf32(acc[mi][nj], al[mi][0], al[mi][1], al[mi][2], al[mi][3], bh0, bh1);
                    mma_tf32(acc[mi][nj], ah[mi][0], ah[mi][1], ah[mi][2], ah[mi][3], bl0, bl1);
                }
            }
        }
    }

#pragma unroll
    for (int mi = 0; mi < 2; mi++) {
        int rloc = m0 + mi * 16 + r;
        float s0 = 0.f, s1 = 0.f;
        if (rloc < nr)     s0 = d_dinv[row0 + rloc];
        if (rloc + 8 < nr) s1 = d_dinv[row0 + rloc + 8];
#pragma unroll
        for (int nj = 0; nj < 4; nj++) {
            int col = n0 + nj * 8 + 2 * c;
            if (rloc < nr)
                *(float2*)(Hout + (size_t)(row0 + rloc) * 128 + col)
                    = make_float2(acc[mi][nj][0] * s0, acc[mi][nj][1] * s0);
            if (rloc + 8 < nr)
                *(float2*)(Hout + (size_t)(row0 + rloc + 8) * 128 + col)
                    = make_float2(acc[mi][nj][2] * s1, acc[mi][nj][3] * s1);
        }
    }
}

// ---------------- aggregation: H is pre-scaled (H' = dinv * XW) ----------------
// out_i = relu(dinv_i * (sum_{e:dst=i} H'[src] + H'[i]) + b)
__global__ __launch_bounds__(256) void aggregate_k(const float* __restrict__ H,
                                                   const float* __restrict__ bias,
                                                   float* __restrict__ outp, int n) {
    int w = (blockIdx.x * blockDim.x + threadIdx.x) >> 5;
    int lane = threadIdx.x & 31;
    if (w >= n) return;
    int beg = d_rowstart[w];
    int end = d_rowstart[w + 1];
    float ax = 0.f, ay = 0.f, az = 0.f, aw = 0.f;
    for (int base = beg; base < end; base += 32) {
        int rem = end - base;
        int idx = (lane < rem) ? d_csr[base + lane] : 0;
        int cnt = rem < 32 ? rem : 32;
        for (int j0 = 0; j0 < cnt; j0 += 8) {
            float4 h[8];
            int m = cnt - j0; if (m > 8) m = 8;
#pragma unroll
            for (int u = 0; u < 8; u++) {
                if (u < m) {
                    int s = __shfl_sync(0xffffffffu, idx, j0 + u);
                    h[u] = *(const float4*)(H + (size_t)s * 128 + lane * 4);
                }
            }
#pragma unroll
            for (int u = 0; u < 8; u++) {
                if (u < m) { ax += h[u].x; ay += h[u].y; az += h[u].z; aw += h[u].w; }
            }
        }
    }
    float4 hs = *(const float4*)(H + (size_t)w * 128 + lane * 4);
    ax += hs.x; ay += hs.y; az += hs.z; aw += hs.w;
    float di = d_dinv[w];
    float4 b4 = *(const float4*)(bias + lane * 4);
    float4 o;
    o.x = fmaxf(di * ax + b4.x, 0.f);
    o.y = fmaxf(di * ay + b4.y, 0.f);
    o.z = fmaxf(di * az + b4.z, 0.f);
    o.w = fmaxf(di * aw + b4.w, 0.f);
    *(float4*)(outp + (size_t)w * 128 + lane * 4) = o;
}

// ---------------- pooling ----------------
__global__ void pool_reduce_k(const float* __restrict__ G, int n) {
    int t = threadIdx.x;  // 128
    float s = 0.f, m = 0.f;  // relu outputs are >= 0
    for (int r = blockIdx.x; r < n; r += gridDim.x) {
        float v = G[(size_t)r * 128 + t];
        s += v;
        m = fmaxf(m, v);
    }
    atomicAdd(&d_scr.poolsum[t], s);
    atomicMax(&d_scr.poolmax[t], __float_as_uint(m));  // valid for nonneg floats
}

__global__ void pool_final_k(int n) {
    int t = threadIdx.x;  // 256
    if (t < 128) d_scr.pool[t] = d_scr.poolsum[t] / (float)n;
    else         d_scr.pool[t] = __uint_as_float(d_scr.poolmax[t - 128]);
}

// ---------------- argmax key helpers ----------------
__device__ __forceinline__ unsigned enc_f(float f) {
    unsigned u = __float_as_uint(f);
    return (u & 0x80000000u) ? ~u : (u | 0x80000000u);
}
__device__ __forceinline__ unsigned long long mkkey(float f, int j) {
    return ((unsigned long long)enc_f(f) << 32) | (unsigned long long)(0xFFFFFFFFu - (unsigned)j);
}

// ---------------- head GEMVs (z1 argmax fused) ----------------
__global__ __launch_bounds__(256) void gemv_heads_k(const float* __restrict__ n1W,
                                                    const float* __restrict__ n1b,
                                                    const float* __restrict__ g1,
                                                    const float* __restrict__ n2W,
                                                    const float* __restrict__ n2b,
                                                    int ncols, int halfblocks) {
    __shared__ float p[256];
    __shared__ unsigned long long redk[256];
    int t = threadIdx.x;
    p[t] = d_scr.pool[t];
    __syncthreads();
    int second = blockIdx.x >= halfblocks;
    int b = second ? blockIdx.x - halfblocks : blockIdx.x;
    int j4 = b * blockDim.x + t;
    bool valid = (j4 * 4 < ncols);
    float ax = 0.f, ay = 0.f, az = 0.f, aw = 0.f;
    if (valid) {
        const float* W = second ? n2W : n1W;
#pragma unroll 4
        for (int k = 0; k < 256; k++) {
            float4 w4 = *(const float4*)(W + (size_t)k * ncols + j4 * 4);
            float pv = p[k];
            ax += pv * w4.x; ay += pv * w4.y; az += pv * w4.z; aw += pv * w4.w;
        }
    }
    int j = j4 * 4;
    if (!second) {
        unsigned long long key = 0ull;
        if (valid) {
            float4 bb = *(const float4*)(n1b + j);
            float4 gg = *(const float4*)(g1 + j);
            float4 o;
            o.x = (ax + bb.x + gg.x) * INV_TAU;
            o.y = (ay + bb.y + gg.y) * INV_TAU;
            o.z = (az + bb.z + gg.z) * INV_TAU;
            o.w = (aw + bb.w + gg.w) * INV_TAU;
            *(float4*)(d_z1 + j) = o;
            key = mkkey(o.x, j);
            unsigned long long k1 = mkkey(o.y, j + 1); if (k1 > key) key = k1;
            unsigned long long k2 = mkkey(o.z, j + 2); if (k2 > key) key = k2;
            unsigned long long k3 = mkkey(o.w, j + 3); if (k3 > key) key = k3;
        }
        redk[t] = key;
        __syncthreads();
        for (int s = 128; s > 0; s >>= 1) {
            if (t < s && redk[t + s] > redk[t]) redk[t] = redk[t + s];
            __syncthreads();
        }
        if (t == 0) atomicMax(&d_scr.best[0], redk[0]);
    } else {
        if (valid) {
            float4 bb = *(const float4*)(n2b + j);
            float4 o;
            o.x = ax + bb.x; o.y = ay + bb.y; o.z = az + bb.z; o.w = aw + bb.w;
            *(float4*)(d_l2 + j) = o;
        }
    }
}

__global__ void decode_k(int which) {
    unsigned long long b = d_scr.best[which];
    unsigned u = (unsigned)(b >> 32);
    unsigned bits = (u & 0x80000000u) ? (u & 0x7FFFFFFFu) : ~u;
    int idx = (int)(0xFFFFFFFFu - (unsigned)(b & 0xFFFFFFFFull));
    d_scr.isel[which] = idx;
    d_scr.zmax[which] = __uint_as_float(bits);
    if (which == 0) d_conn[idx] = 1;
}

// ---------------- mask of nodes connected to i1 ----------------
__global__ void conn_k(const int* __restrict__ srcp, const int* __restrict__ dstp, int E) {
    int i1 = d_scr.isel[0];
    int e = blockIdx.x * blockDim.x + threadIdx.x;
    if (e < E) {
        int s = srcp[e], d = dstp[e];
        if (s == i1 || d == i1) { d_conn[s] = 1; d_conn[d] = 1; }
    }
}

// z2 compute + fused argmax
__global__ void z2argmax_k(const float* __restrict__ g2, int n) {
    __shared__ unsigned long long sm[256];
    int t = threadIdx.x;
    unsigned long long best = 0ull;
    for (int j = blockIdx.x * blockDim.x + t; j < n; j += gridDim.x * blockDim.x) {
        float l = d_conn[j] ? MASKV : d_l2[j];
        float z = (l + g2[j]) * INV_TAU;
        d_z2[j] = z;
        unsigned long long key = mkkey(z, j);
        if (key > best) best = key;
    }
    sm[t] = best;
    __syncthreads();
    for (int s = 128; s > 0; s >>= 1) {
        if (t < s && sm[t + s] > sm[t]) sm[t] = sm[t + s];
        __syncthreads();
    }
    if (t == 0) atomicMax(&d_scr.best[1], sm[0]);
}

// ---------------- softmax (exp + sum, then normalize) ----------------
__global__ void exp_k(const float* __restrict__ z, float* __restrict__ outp, int n, int which) {
    __shared__ float sm[256];
    int t = threadIdx.x;
    float zm = d_scr.zmax[which];
    float ls = 0.f;
    for (int j = blockIdx.x * blockDim.x + t; j < n; j += gridDim.x * blockDim.x) {
        float e = expf(z[j] - zm);
        outp[j] = e;
        ls += e;
    }
    sm[t] = ls;
    __syncthreads();
    for (int s = 128; s > 0; s >>= 1) {
        if (t < s) sm[t] += sm[t + s];
        __syncthreads();
    }
    if (t == 0) atomicAdd(&d_scr.S[which], sm[0]);
}

__global__ void norm_k(float* __restrict__ outp, int n, int which) {
    float inv = 1.0f / d_scr.S[which];
    int j = blockIdx.x * blockDim.x + threadIdx.x;
    if (j < n) outp[j] *= inv;
}

// ---------------- edge-type head + stop head ----------------
__global__ void esoft_k(const float* __restrict__ G, const float* __restrict__ eW,
                        const float* __restrict__ eb, const float* __restrict__ ge,
                        float* __restrict__ outp, int n) {
    __shared__ float red[3][128];
    int t = threadIdx.x;  // 128
    int i1 = d_scr.isel[0];
    int i2 = d_scr.isel[1];
    float a = G[(size_t)i1 * 128 + t];
    float b = G[(size_t)i2 * 128 + t];
#pragma unroll
    for (int o = 0; o < 3; o++)
        red[o][t] = a * eW[t * 3 + o] + b * eW[(128 + t) * 3 + o];
    __syncthreads();
    for (int s = 64; s > 0; s >>= 1) {
        if (t < s) {
            red[0][t] += red[0][t + s];
            red[1][t] += red[1][t + s];
            red[2][t] += red[2][t + s];
        }
        __syncthreads();
    }
    if (t == 0) {
        float z0 = (red[0][0] + eb[0] + ge[0]) * INV_TAU;
        float z1v = (red[1][0] + eb[1] + ge[1]) * INV_TAU;
        float z2v = (red[2][0] + eb[2] + ge[2]) * INV_TAU;
        float m = fmaxf(z0, fmaxf(z1v, z2v));
        float e0 = expf(z0 - m), e1 = expf(z1v - m), e2 = expf(z2v - m);
        float inv = 1.0f / (e0 + e1 + e2);
        outp[2 * n + 0] = e0 * inv;
        outp[2 * n + 1] = e1 * inv;
        outp[2 * n + 2] = e2 * inv;
        outp[2 * n + 3] = 1.0f;  // softmax over a single logit == 1
    }
}

// ---------------- launcher ----------------
extern "C" void kernel_launch(void* const* d_in, const int* in_sizes, int n_in,
                              void* d_out, int out_size) {
    const float* x   = (const float*)d_in[0];
    const int*   ei  = (const int*)  d_in[1];
    const float* W1  = (const float*)d_in[2];
    const float* b1  = (const float*)d_in[3];
    const float* W2  = (const float*)d_in[4];
    const float* b2  = (const float*)d_in[5];
    const float* W3  = (const float*)d_in[6];
    const float* b3  = (const float*)d_in[7];
    const float* n1W = (const float*)d_in[8];
    const float* n1b = (const float*)d_in[9];
    const float* n2W = (const float*)d_in[10];
    const float* n2b = (const float*)d_in[11];
    const float* eW  = (const float*)d_in[12];
    const float* eb  = (const float*)d_in[13];
    const float* g1  = (const float*)d_in[16];
    const float* g2  = (const float*)d_in[17];
    const float* ge  = (const float*)d_in[18];
    float* out = (float*)d_out;

    int n = in_sizes[0] / 128;
    int E = in_sizes[1] / 2;
    const int* srcp = ei;
    const int* dstp = ei + E;

    void *pc, *pconn, *pscr, *pH, *pXA, *pXB, *pz1, *pz2;
    cudaGetSymbolAddress(&pc,    d_counts);
    cudaGetSymbolAddress(&pconn, d_conn);
    cudaGetSymbolAddress(&pscr,  d_scr);
    cudaGetSymbolAddress(&pH,    d_H);
    cudaGetSymbolAddress(&pXA,   d_XA);
    cudaGetSymbolAddress(&pXB,   d_XB);
    cudaGetSymbolAddress(&pz1,   d_z1);
    cudaGetSymbolAddress(&pz2,   d_z2);
    float* H  = (float*)pH;
    float* XA = (float*)pXA;
    float* XB = (float*)pXB;
    const float* z1p = (const float*)pz1;
    const float* z2p = (const float*)pz2;

    const int GEMM_SMEM = (2 * 64 * XH_ST + 2 * 64 * WH_ST) * 4;  // 104448 B
    cudaFuncSetAttribute(gemm_tf32_k, cudaFuncAttributeMaxDynamicSharedMemorySize, GEMM_SMEM);

    cudaMemsetAsync(pc,    0, (size_t)n * sizeof(int), 0);
    cudaMemsetAsync(pconn, 0, (size_t)n, 0);
    cudaMemsetAsync(pscr,  0, sizeof(Scr), 0);

    int eblocks = (E + 255) / 256;
    int nb = (n + 1023) / 1024;
    degcount_k<<<eblocks, 256>>>(dstp, E);
    scan1_k<<<nb, 1024>>>(n);
    scan2_k<<<1, 128>>>(nb, n);
    scan3_k<<<nb, 1024>>>(n);
    fill_csr_k<<<eblocks, 256>>>(srcp, dstp, E);

    int gblocks = (n + 63) / 64;
    int ablocks = (n + 7) / 8;  // warp per node, 8 warps/block

    gemm_tf32_k<<<gblocks, 256, GEMM_SMEM>>>(x,  W1, H, n);
    aggregate_k<<<ablocks, 256>>>(H, b1, XA, n);
    gemm_tf32_k<<<gblocks, 256, GEMM_SMEM>>>(XA, W2, H, n);
    aggregate_k<<<ablocks, 256>>>(H, b2, XB, n);
    gemm_tf32_k<<<gblocks, 256, GEMM_SMEM>>>(XB, W3, H, n);
    aggregate_k<<<ablocks, 256>>>(H, b3, XA, n);  // XA = gcn

    pool_reduce_k<<<512, 128>>>(XA, n);
    pool_final_k<<<1, 256>>>(n);

    int halfblocks = (n / 4 + 255) / 256;
    gemv_heads_k<<<2 * halfblocks, 256>>>(n1W, n1b, g1, n2W, n2b, n, halfblocks);

    decode_k<<<1, 1>>>(0);
    conn_k<<<eblocks, 256>>>(srcp, dstp, E);
    exp_k<<<256, 256>>>(z1p, out, n, 0);
    norm_k<<<(n + 255) / 256, 256>>>(out, n, 0);

    z2argmax_k<<<256, 256>>>(g2, n);
    decode_k<<<1, 1>>>(1);
    exp_k<<<256, 256>>>(z2p, out + n, n, 1);
    norm_k<<<(n + 255) / 256, 256>>>(out + n, n, 1);

    esoft_k<<<1, 128>>>(XA, eW, eb, ge, out, n);
}

// round 4
// speedup vs baseline: 1.2050x; 1.0391x over previous
#include <cuda_runtime.h>
#include <cuda_bf16.h>

#define NMAX 100000
#define EMAX 1600000
#define MASKV (-1000000000.0f)
#define INV_TAU 2.0f

// ---------------- device scratch (static allocation only) ----------------
struct Scr {
    float poolsum[128];
    unsigned int poolmax[128];
    float zmax[2];
    float S[2];
    int isel[2];
};

__device__ float d_H [NMAX * 128];
__device__ float d_XA[NMAX * 128];
__device__ float d_XB[NMAX * 128];
__device__ int   d_counts[NMAX];
__device__ int   d_rowstart[NMAX + 1];
__device__ int   d_cursor[NMAX];
__device__ int   d_csr[EMAX];
__device__ float d_dinv[NMAX];
__device__ float d_z1[NMAX];
__device__ float d_l2[NMAX];
__device__ float d_z2[NMAX];
__device__ unsigned char d_conn[NMAX];
__device__ int   d_bsum[128];
__device__ int   d_boff[128];
__device__ float d_bm[2][128];
__device__ float d_bs[2][128];
__device__ unsigned long long d_bk[2][128];
__device__ Scr   d_scr;

// ---------------- CSR build ----------------
__global__ void degcount_k(const int* __restrict__ dstp, int E) {
    int e = blockIdx.x * blockDim.x + threadIdx.x;
    if (e < E) atomicAdd(&d_counts[dstp[e]], 1);
}

__global__ void scan1_k(int n) {
    __shared__ int sm[1024];
    int t = threadIdx.x;
    int i = blockIdx.x * 1024 + t;
    int v = (i < n) ? d_counts[i] : 0;
    sm[t] = v;
    __syncthreads();
    for (int s = 512; s > 0; s >>= 1) {
        if (t < s) sm[t] += sm[t + s];
        __syncthreads();
    }
    if (t == 0) d_bsum[blockIdx.x] = sm[0];
}

__global__ void scan2_k(int nb, int n) {
    __shared__ int sm[128];
    int t = threadIdx.x;
    int v = (t < nb) ? d_bsum[t] : 0;
    sm[t] = v;
    __syncthreads();
    for (int d = 1; d < 128; d <<= 1) {
        int add = (t >= d) ? sm[t - d] : 0;
        __syncthreads();
        sm[t] += add;
        __syncthreads();
    }
    if (t < nb) d_boff[t] = sm[t] - v;
    if (t == nb - 1) d_rowstart[n] = sm[t];
}

__global__ void scan3_k(int n) {
    __shared__ int sm[1024];
    int t = threadIdx.x;
    int i = blockIdx.x * 1024 + t;
    int v = (i < n) ? d_counts[i] : 0;
    sm[t] = v;
    __syncthreads();
    for (int d = 1; d < 1024; d <<= 1) {
        int add = (t >= d) ? sm[t - d] : 0;
        __syncthreads();
        sm[t] += add;
        __syncthreads();
    }
    if (i < n) {
        int excl = sm[t] - v + d_boff[blockIdx.x];
        d_rowstart[i] = excl;
        d_cursor[i]   = excl;
        d_dinv[i]     = rsqrtf((float)v + 1.0f);
    }
}

__global__ void fill_csr_k(const int* __restrict__ srcp, const int* __restrict__ dstp, int E) {
    int e = blockIdx.x * blockDim.x + threadIdx.x;
    if (e < E) {
        int d = dstp[e];
        int pos = atomicAdd(&d_cursor[d], 1);
        d_csr[pos] = srcp[e];
    }
}

// ---------------- 3xTF32 tensor-core GEMM, smem hi/lo, chunk prefetch ------
// Hout[i,:] = dinv[i] * (X @ W)[i,:]
#define XH_ST 68
#define WH_ST 136

__device__ __forceinline__ unsigned f2tf32(float f) {
    unsigned r;
    asm("cvt.rna.tf32.f32 %0, %1;" : "=r"(r) : "f"(f));
    return r;
}

__device__ __forceinline__ void mma_tf32(float* d,
                                         unsigned a0, unsigned a1, unsigned a2, unsigned a3,
                                         unsigned b0, unsigned b1) {
    asm volatile("mma.sync.aligned.m16n8k8.row.col.f32.tf32.tf32.f32 "
                 "{%0,%1,%2,%3}, {%4,%5,%6,%7}, {%8,%9}, {%0,%1,%2,%3};"
                 : "+f"(d[0]), "+f"(d[1]), "+f"(d[2]), "+f"(d[3])
                 : "r"(a0), "r"(a1), "r"(a2), "r"(a3), "r"(b0), "r"(b1));
}

__device__ __forceinline__ void split4(float4 v, float4& hi, float4& lo) {
    hi.x = __uint_as_float(f2tf32(v.x)); lo.x = __uint_as_float(f2tf32(v.x - hi.x));
    hi.y = __uint_as_float(f2tf32(v.y)); lo.y = __uint_as_float(f2tf32(v.y - hi.y));
    hi.z = __uint_as_float(f2tf32(v.z)); lo.z = __uint_as_float(f2tf32(v.z - hi.z));
    hi.w = __uint_as_float(f2tf32(v.w)); lo.w = __uint_as_float(f2tf32(v.w - hi.w));
}

__device__ __forceinline__ void compute_chunk(const float* xh, const float* xl,
                                              const float* wh, const float* wl,
                                              float acc[2][4][4],
                                              int m0, int n0, int r, int c) {
#pragma unroll
    for (int kk = 0; kk < 64; kk += 8) {
        unsigned ah[2][4], al[2][4];
#pragma unroll
        for (int mi = 0; mi < 2; mi++) {
            const float* xb  = xh + (m0 + mi * 16 + r) * XH_ST + c + kk;
            const float* xlb = xl + (m0 + mi * 16 + r) * XH_ST + c + kk;
            ah[mi][0] = __float_as_uint(xb[0]);
            ah[mi][1] = __float_as_uint(xb[8 * XH_ST]);
            ah[mi][2] = __float_as_uint(xb[4]);
            ah[mi][3] = __float_as_uint(xb[8 * XH_ST + 4]);
            al[mi][0] = __float_as_uint(xlb[0]);
            al[mi][1] = __float_as_uint(xlb[8 * XH_ST]);
            al[mi][2] = __float_as_uint(xlb[4]);
            al[mi][3] = __float_as_uint(xlb[8 * XH_ST + 4]);
        }
#pragma unroll
        for (int nj = 0; nj < 4; nj++) {
            const float* wb  = wh + (kk + c) * WH_ST + n0 + nj * 8 + r;
            const float* wlb = wl + (kk + c) * WH_ST + n0 + nj * 8 + r;
            unsigned bh0 = __float_as_uint(wb[0]);
            unsigned bh1 = __float_as_uint(wb[4 * WH_ST]);
            unsigned bl0 = __float_as_uint(wlb[0]);
            unsigned bl1 = __float_as_uint(wlb[4 * WH_ST]);
#pragma unroll
            for (int mi = 0; mi < 2; mi++) {
                mma_tf32(acc[mi][nj], ah[mi][0], ah[mi][1], ah[mi][2], ah[mi][3], bh0, bh1);
                mma_tf32(acc[mi][nj], al[mi][0], al[mi][1], al[mi][2], al[mi][3], bh0, bh1);
                mma_tf32(acc[mi][nj], ah[mi][0], ah[mi][1], ah[mi][2], ah[mi][3], bl0, bl1);
            }
        }
    }
}

__global__ __launch_bounds__(256, 2) void gemm_tf32_k(const float* __restrict__ X,
                                                      const float* __restrict__ W,
                                                      float* __restrict__ Hout, int n) {
    extern __shared__ float sh[];
    float* xh = sh;                         // 64 x XH_ST
    float* xl = xh + 64 * XH_ST;
    float* wh = xl + 64 * XH_ST;            // 64 x WH_ST
    float* wl = wh + 64 * WH_ST;

    int t = threadIdx.x;
    int row0 = blockIdx.x * 64;
    int nr = n - row0; if (nr > 64) nr = 64;

    int lane = t & 31, wid = t >> 5;
    int wm = wid & 1, wn = wid >> 1;
    int m0 = wm * 32, n0 = wn * 32;
    int r = lane >> 2, c = lane & 3;

    float acc[2][4][4];
#pragma unroll
    for (int mi = 0; mi < 2; mi++)
#pragma unroll
        for (int nj = 0; nj < 4; nj++)
#pragma unroll
            for (int q = 0; q < 4; q++) acc[mi][nj][q] = 0.f;

    // chunk 0 loads -> smem (split hi/lo)
    for (int i = t; i < 2048; i += 256) {
        int k = i >> 5, c4 = i & 31;
        float4 v = *(const float4*)(W + (size_t)k * 128 + c4 * 4);
        float4 hi, lo; split4(v, hi, lo);
        *(float4*)(wh + k * WH_ST + c4 * 4) = hi;
        *(float4*)(wl + k * WH_ST + c4 * 4) = lo;
    }
    for (int i = t; i < nr * 16; i += 256) {
        int rr = i >> 4, c4 = i & 15;
        float4 v = *(const float4*)(X + (size_t)(row0 + rr) * 128 + c4 * 4);
        float4 hi, lo; split4(v, hi, lo);
        *(float4*)(xh + rr * XH_ST + c4 * 4) = hi;
        *(float4*)(xl + rr * XH_ST + c4 * 4) = lo;
    }
    __syncthreads();

    // prefetch chunk 1 into registers (overlaps with chunk-0 compute)
    float4 wreg[8], xreg[4];
#pragma unroll
    for (int u = 0; u < 8; u++) {
        int i = t + u * 256;
        int k = i >> 5, c4 = i & 31;
        wreg[u] = *(const float4*)(W + (size_t)(64 + k) * 128 + c4 * 4);
    }
#pragma unroll
    for (int u = 0; u < 4; u++) {
        int i = t + u * 256;
        if (i < nr * 16) {
            int rr = i >> 4, c4 = i & 15;
            xreg[u] = *(const float4*)(X + (size_t)(row0 + rr) * 128 + 64 + c4 * 4);
        }
    }

    compute_chunk(xh, xl, wh, wl, acc, m0, n0, r, c);
    __syncthreads();

    // store chunk 1 to smem
#pragma unroll
    for (int u = 0; u < 8; u++) {
        int i = t + u * 256;
        int k = i >> 5, c4 = i & 31;
        float4 hi, lo; split4(wreg[u], hi, lo);
        *(float4*)(wh + k * WH_ST + c4 * 4) = hi;
        *(float4*)(wl + k * WH_ST + c4 * 4) = lo;
    }
#pragma unroll
    for (int u = 0; u < 4; u++) {
        int i = t + u * 256;
        if (i < nr * 16) {
            int rr = i >> 4, c4 = i & 15;
            float4 hi, lo; split4(xreg[u], hi, lo);
            *(float4*)(xh + rr * XH_ST + c4 * 4) = hi;
            *(float4*)(xl + rr * XH_ST + c4 * 4) = lo;
        }
    }
    __syncthreads();

    compute_chunk(xh, xl, wh, wl, acc, m0, n0, r, c);

#pragma unroll
    for (int mi = 0; mi < 2; mi++) {
        int rloc = m0 + mi * 16 + r;
        float s0 = 0.f, s1 = 0.f;
        if (rloc < nr)     s0 = d_dinv[row0 + rloc];
        if (rloc + 8 < nr) s1 = d_dinv[row0 + rloc + 8];
#pragma unroll
        for (int nj = 0; nj < 4; nj++) {
            int col = n0 + nj * 8 + 2 * c;
            if (rloc < nr)
                *(float2*)(Hout + (size_t)(row0 + rloc) * 128 + col)
                    = make_float2(acc[mi][nj][0] * s0, acc[mi][nj][1] * s0);
            if (rloc + 8 < nr)
                *(float2*)(Hout + (size_t)(row0 + rloc + 8) * 128 + col)
                    = make_float2(acc[mi][nj][2] * s1, acc[mi][nj][3] * s1);
        }
    }
}

// ---------------- aggregation (pipelined gather) + optional pool fusion ----
// out_i = relu(dinv_i * (sum_{e:dst=i} H'[src] + H'[i]) + b)
__global__ __launch_bounds__(256) void aggregate_k(const float* __restrict__ H,
                                                   const float* __restrict__ bias,
                                                   float* __restrict__ outp, int n,
                                                   int dopool) {
    __shared__ float pS[8][128];
    __shared__ float pM[8][128];
    int t = threadIdx.x;
    int w = (blockIdx.x * blockDim.x + t) >> 5;
    int lane = t & 31;
    int wid = t >> 5;

    float4 o = make_float4(0.f, 0.f, 0.f, 0.f);
    if (w < n) {
        int beg = d_rowstart[w];
        int end = d_rowstart[w + 1];
        float ax = 0.f, ay = 0.f, az = 0.f, aw = 0.f;
        for (int base = beg; base < end; base += 32) {
            int rem = end - base;
            int cnt = rem < 32 ? rem : 32;
            int idx = (lane < cnt) ? d_csr[base + lane] : 0;
            float4 h[4];
            int m0 = cnt < 4 ? cnt : 4;
#pragma unroll
            for (int u = 0; u < 4; u++) {
                if (u < m0) {
                    int s = __shfl_sync(0xffffffffu, idx, u);
                    h[u] = *(const float4*)(H + (size_t)s * 128 + lane * 4);
                }
            }
            for (int j0 = 0; j0 < cnt; j0 += 4) {
                int curm = cnt - j0; if (curm > 4) curm = 4;
                int nxtm = cnt - j0 - 4; if (nxtm > 4) nxtm = 4;
                float4 h2[4];
#pragma unroll
                for (int u = 0; u < 4; u++) {
                    if (u < nxtm) {
                        int s = __shfl_sync(0xffffffffu, idx, j0 + 4 + u);
                        h2[u] = *(const float4*)(H + (size_t)s * 128 + lane * 4);
                    }
                }
#pragma unroll
                for (int u = 0; u < 4; u++) {
                    if (u < curm) { ax += h[u].x; ay += h[u].y; az += h[u].z; aw += h[u].w; }
                }
#pragma unroll
                for (int u = 0; u < 4; u++) h[u] = h2[u];
            }
        }
        float4 hs = *(const float4*)(H + (size_t)w * 128 + lane * 4);
        ax += hs.x; ay += hs.y; az += hs.z; aw += hs.w;
        float di = d_dinv[w];
        float4 b4 = *(const float4*)(bias + lane * 4);
        o.x = fmaxf(di * ax + b4.x, 0.f);
        o.y = fmaxf(di * ay + b4.y, 0.f);
        o.z = fmaxf(di * az + b4.z, 0.f);
        o.w = fmaxf(di * aw + b4.w, 0.f);
        *(float4*)(outp + (size_t)w * 128 + lane * 4) = o;
    }

    if (dopool) {
        pS[wid][lane * 4 + 0] = o.x; pM[wid][lane * 4 + 0] = o.x;
        pS[wid][lane * 4 + 1] = o.y; pM[wid][lane * 4 + 1] = o.y;
        pS[wid][lane * 4 + 2] = o.z; pM[wid][lane * 4 + 2] = o.z;
        pS[wid][lane * 4 + 3] = o.w; pM[wid][lane * 4 + 3] = o.w;
        __syncthreads();
        if (t < 128) {
            float s = 0.f, mx = 0.f;
#pragma unroll
            for (int u = 0; u < 8; u++) { s += pS[u][t]; mx = fmaxf(mx, pM[u][t]); }
            atomicAdd(&d_scr.poolsum[t], s);
            atomicMax(&d_scr.poolmax[t], __float_as_uint(mx));
        }
    }
}

// ---------------- argmax key helpers ----------------
__device__ __forceinline__ unsigned enc_f(float f) {
    unsigned u = __float_as_uint(f);
    return (u & 0x80000000u) ? ~u : (u | 0x80000000u);
}
__device__ __forceinline__ unsigned long long mkkey(float f, int j) {
    return ((unsigned long long)enc_f(f) << 32) | (unsigned long long)(0xFFFFFFFFu - (unsigned)j);
}

// ---------------- head GEMVs + inline pool final + z1 block stats ----------
__global__ __launch_bounds__(256) void gemv_heads_k(const float* __restrict__ n1W,
                                                    const float* __restrict__ n1b,
                                                    const float* __restrict__ g1,
                                                    const float* __restrict__ n2W,
                                                    const float* __restrict__ n2b,
                                                    int ncols, int halfblocks, float inv_n) {
    __shared__ float p[256];
    __shared__ float red[256];
    __shared__ unsigned long long redk[256];
    int t = threadIdx.x;
    if (t < 128) p[t] = d_scr.poolsum[t] * inv_n;
    else         p[t] = __uint_as_float(d_scr.poolmax[t - 128]);
    __syncthreads();
    int second = blockIdx.x >= halfblocks;
    int b = second ? blockIdx.x - halfblocks : blockIdx.x;
    int j4 = b * blockDim.x + t;
    bool valid = (j4 * 4 < ncols);
    float ax = 0.f, ay = 0.f, az = 0.f, aw = 0.f;
    if (valid) {
        const float* W = second ? n2W : n1W;
#pragma unroll 4
        for (int k = 0; k < 256; k++) {
            float4 w4 = *(const float4*)(W + (size_t)k * ncols + j4 * 4);
            float pv = p[k];
            ax += pv * w4.x; ay += pv * w4.y; az += pv * w4.z; aw += pv * w4.w;
        }
    }
    int j = j4 * 4;
    if (!second) {
        float4 o = make_float4(0.f, 0.f, 0.f, 0.f);
        if (valid) {
            float4 bb = *(const float4*)(n1b + j);
            float4 gg = *(const float4*)(g1 + j);
            o.x = (ax + bb.x + gg.x) * INV_TAU;
            o.y = (ay + bb.y + gg.y) * INV_TAU;
            o.z = (az + bb.z + gg.z) * INV_TAU;
            o.w = (aw + bb.w + gg.w) * INV_TAU;
            *(float4*)(d_z1 + j) = o;
        }
        // block max
        float lm = valid ? fmaxf(fmaxf(o.x, o.y), fmaxf(o.z, o.w)) : -1e30f;
        red[t] = lm;
        __syncthreads();
        for (int s = 128; s > 0; s >>= 1) {
            if (t < s) red[t] = fmaxf(red[t], red[t + s]);
            __syncthreads();
        }
        float bm = red[0];
        __syncthreads();
        // block sum of exp(z - bm)
        float ls = 0.f;
        if (valid) {
            ls = expf(o.x - bm) + expf(o.y - bm) + expf(o.z - bm) + expf(o.w - bm);
        }
        red[t] = ls;
        // block argmax key
        unsigned long long key = 0ull;
        if (valid) {
            key = mkkey(o.x, j);
            unsigned long long k1 = mkkey(o.y, j + 1); if (k1 > key) key = k1;
            unsigned long long k2 = mkkey(o.z, j + 2); if (k2 > key) key = k2;
            unsigned long long k3 = mkkey(o.w, j + 3); if (k3 > key) key = k3;
        }
        redk[t] = key;
        __syncthreads();
        for (int s = 128; s > 0; s >>= 1) {
            if (t < s) {
                red[t] += red[t + s];
                if (redk[t + s] > redk[t]) redk[t] = redk[t + s];
            }
            __syncthreads();
        }
        if (t == 0) {
            d_bm[0][b] = bm;
            d_bs[0][b] = red[0];
            d_bk[0][b] = redk[0];
        }
    } else {
        if (valid) {
            float4 bb = *(const float4*)(n2b + j);
            float4 o;
            o.x = ax + bb.x; o.y = ay + bb.y; o.z = az + bb.z; o.w = aw + bb.w;
            *(float4*)(d_l2 + j) = o;
        }
    }
}

// ---------------- merge block stats -> global M, S, argmax ----------------
__global__ void merge_k(int which, int nb) {
    __shared__ float sm[128];
    __shared__ float ss[128];
    __shared__ unsigned long long sk[128];
    int t = threadIdx.x;  // 128
    float m = (t < nb) ? d_bm[which][t] : -1e30f;
    sm[t] = m;
    __syncthreads();
    for (int s = 64; s > 0; s >>= 1) {
        if (t < s) sm[t] = fmaxf(sm[t], sm[t + s]);
        __syncthreads();
    }
    float M = sm[0];
    __syncthreads();
    float ls = (t < nb) ? d_bs[which][t] * expf(d_bm[which][t] - M) : 0.f;
    ss[t] = ls;
    sk[t] = (t < nb) ? d_bk[which][t] : 0ull;
    __syncthreads();
    for (int s = 64; s > 0; s >>= 1) {
        if (t < s) {
            ss[t] += ss[t + s];
            if (sk[t + s] > sk[t]) sk[t] = sk[t + s];
        }
        __syncthreads();
    }
    if (t == 0) {
        d_scr.zmax[which] = M;
        d_scr.S[which] = ss[0];
        int idx = (int)(0xFFFFFFFFu - (unsigned)(sk[0] & 0xFFFFFFFFull));
        d_scr.isel[which] = idx;
        if (which == 0) d_conn[idx] = 1;
    }
}

// ---------------- mask of nodes connected to i1 ----------------
__global__ void conn_k(const int* __restrict__ srcp, const int* __restrict__ dstp, int E) {
    int i1 = d_scr.isel[0];
    int e = blockIdx.x * blockDim.x + threadIdx.x;
    if (e < E) {
        int s = srcp[e], d = dstp[e];
        if (s == i1 || d == i1) { d_conn[s] = 1; d_conn[d] = 1; }
    }
}

// ---------------- fused A: [write n1_soft] || [z2 compute + block stats] ----
__global__ __launch_bounds__(256) void fused_a_k(const float* __restrict__ g2,
                                                 float* __restrict__ outp, int n, int WB) {
    __shared__ float red[256];
    __shared__ unsigned long long redk[256];
    int t = threadIdx.x;
    if ((int)blockIdx.x < WB) {
        // write pass for n1_soft
        float M = d_scr.zmax[0];
        float invS = 1.0f / d_scr.S[0];
        int j4 = blockIdx.x * 256 + t;
        int j = j4 * 4;
        if (j < n) {
            float4 z = *(const float4*)(d_z1 + j);
            float4 o;
            o.x = expf(z.x - M) * invS;
            o.y = expf(z.y - M) * invS;
            o.z = expf(z.z - M) * invS;
            o.w = expf(z.w - M) * invS;
            *(float4*)(outp + j) = o;
        }
        return;
    }
    // z2 compute + stats
    int b = blockIdx.x - WB;
    int j4 = b * 256 + t;
    int j = j4 * 4;
    bool valid = (j < n);
    float4 z = make_float4(0.f, 0.f, 0.f, 0.f);
    if (valid) {
        float4 l = *(const float4*)(d_l2 + j);
        uchar4 cn = *(const uchar4*)(d_conn + j);
        float4 g = *(const float4*)(g2 + j);
        z.x = ((cn.x ? MASKV : l.x) + g.x) * INV_TAU;
        z.y = ((cn.y ? MASKV : l.y) + g.y) * INV_TAU;
        z.z = ((cn.z ? MASKV : l.z) + g.z) * INV_TAU;
        z.w = ((cn.w ? MASKV : l.w) + g.w) * INV_TAU;
        *(float4*)(d_z2 + j) = z;
    }
    float lm = valid ? fmaxf(fmaxf(z.x, z.y), fmaxf(z.z, z.w)) : -1e30f;
    red[t] = lm;
    __syncthreads();
    for (int s = 128; s > 0; s >>= 1) {
        if (t < s) red[t] = fmaxf(red[t], red[t + s]);
        __syncthreads();
    }
    float bm = red[0];
    __syncthreads();
    float ls = 0.f;
    if (valid) ls = expf(z.x - bm) + expf(z.y - bm) + expf(z.z - bm) + expf(z.w - bm);
    red[t] = ls;
    unsigned long long key = 0ull;
    if (valid) {
        key = mkkey(z.x, j);
        unsigned long long k1 = mkkey(z.y, j + 1); if (k1 > key) key = k1;
        unsigned long long k2 = mkkey(z.z, j + 2); if (k2 > key) key = k2;
        unsigned long long k3 = mkkey(z.w, j + 3); if (k3 > key) key = k3;
    }
    redk[t] = key;
    __syncthreads();
    for (int s = 128; s > 0; s >>= 1) {
        if (t < s) {
            red[t] += red[t + s];
            if (redk[t + s] > redk[t]) redk[t] = redk[t + s];
        }
        __syncthreads();
    }
    if (t == 0) {
        d_bm[1][b] = bm;
        d_bs[1][b] = red[0];
        d_bk[1][b] = redk[0];
    }
}

// ---------------- fused B: [esoft] || [write n2_soft] ----------------
__global__ __launch_bounds__(256) void fused_b_k(const float* __restrict__ G,
                                                 const float* __restrict__ eW,
                                                 const float* __restrict__ eb,
                                                 const float* __restrict__ ge,
                                                 float* __restrict__ outp, int n) {
    int t = threadIdx.x;
    if (blockIdx.x == 0) {
        __shared__ float red3[3][128];
        int i1 = d_scr.isel[0];
        int i2 = d_scr.isel[1];
        if (t < 128) {
            float a = G[(size_t)i1 * 128 + t];
            float b = G[(size_t)i2 * 128 + t];
#pragma unroll
            for (int o = 0; o < 3; o++)
                red3[o][t] = a * eW[t * 3 + o] + b * eW[(128 + t) * 3 + o];
        }
        __syncthreads();
        for (int s = 64; s > 0; s >>= 1) {
            if (t < s) {
                red3[0][t] += red3[0][t + s];
                red3[1][t] += red3[1][t + s];
                red3[2][t] += red3[2][t + s];
            }
            __syncthreads();
        }
        if (t == 0) {
            float z0 = (red3[0][0] + eb[0] + ge[0]) * INV_TAU;
            float z1v = (red3[1][0] + eb[1] + ge[1]) * INV_TAU;
            float z2v = (red3[2][0] + eb[2] + ge[2]) * INV_TAU;
            float m = fmaxf(z0, fmaxf(z1v, z2v));
            float e0 = expf(z0 - m), e1 = expf(z1v - m), e2 = expf(z2v - m);
            float inv = 1.0f / (e0 + e1 + e2);
            outp[2 * n + 0] = e0 * inv;
            outp[2 * n + 1] = e1 * inv;
            outp[2 * n + 2] = e2 * inv;
            outp[2 * n + 3] = 1.0f;
        }
        return;
    }
    // write n2_soft
    float M = d_scr.zmax[1];
    float invS = 1.0f / d_scr.S[1];
    int j4 = (blockIdx.x - 1) * 256 + t;
    int j = j4 * 4;
    if (j < n) {
        float4 z = *(const float4*)(d_z2 + j);
        float4 o;
        o.x = expf(z.x - M) * invS;
        o.y = expf(z.y - M) * invS;
        o.z = expf(z.z - M) * invS;
        o.w = expf(z.w - M) * invS;
        *(float4*)(outp + n + j) = o;
    }
}

// ---------------- launcher ----------------
extern "C" void kernel_launch(void* const* d_in, const int* in_sizes, int n_in,
                              void* d_out, int out_size) {
    const float* x   = (const float*)d_in[0];
    const int*   ei  = (const int*)  d_in[1];
    const float* W1  = (const float*)d_in[2];
    const float* b1  = (const float*)d_in[3];
    const float* W2  = (const float*)d_in[4];
    const float* b2  = (const float*)d_in[5];
    const float* W3  = (const float*)d_in[6];
    const float* b3  = (const float*)d_in[7];
    const float* n1W = (const float*)d_in[8];
    const float* n1b = (const float*)d_in[9];
    const float* n2W = (const float*)d_in[10];
    const float* n2b = (const float*)d_in[11];
    const float* eW  = (const float*)d_in[12];
    const float* eb  = (const float*)d_in[13];
    const float* g1  = (const float*)d_in[16];
    const float* g2  = (const float*)d_in[17];
    const float* ge  = (const float*)d_in[18];
    float* out = (float*)d_out;

    int n = in_sizes[0] / 128;
    int E = in_sizes[1] / 2;
    const int* srcp = ei;
    const int* dstp = ei + E;

    void *pc, *pconn, *pscr, *pH, *pXA, *pXB;
    cudaGetSymbolAddress(&pc,    d_counts);
    cudaGetSymbolAddress(&pconn, d_conn);
    cudaGetSymbolAddress(&pscr,  d_scr);
    cudaGetSymbolAddress(&pH,    d_H);
    cudaGetSymbolAddress(&pXA,   d_XA);
    cudaGetSymbolAddress(&pXB,   d_XB);
    float* H  = (float*)pH;
    float* XA = (float*)pXA;
    float* XB = (float*)pXB;

    const int GEMM_SMEM = (2 * 64 * XH_ST + 2 * 64 * WH_ST) * 4;  // 104448 B
    cudaFuncSetAttribute(gemm_tf32_k, cudaFuncAttributeMaxDynamicSharedMemorySize, GEMM_SMEM);

    cudaMemsetAsync(pc,    0, (size_t)n * sizeof(int), 0);
    cudaMemsetAsync(pconn, 0, (size_t)n, 0);
    cudaMemsetAsync(pscr,  0, sizeof(Scr), 0);

    int eblocks = (E + 255) / 256;
    int nb = (n + 1023) / 1024;
    degcount_k<<<eblocks, 256>>>(dstp, E);
    scan1_k<<<nb, 1024>>>(n);
    scan2_k<<<1, 128>>>(nb, n);
    scan3_k<<<nb, 1024>>>(n);
    fill_csr_k<<<eblocks, 256>>>(srcp, dstp, E);

    int gblocks = (n + 63) / 64;
    int ablocks = (n + 7) / 8;

    gemm_tf32_k<<<gblocks, 256, GEMM_SMEM>>>(x,  W1, H, n);
    aggregate_k<<<ablocks, 256>>>(H, b1, XA, n, 0);
    gemm_tf32_k<<<gblocks, 256, GEMM_SMEM>>>(XA, W2, H, n);
    aggregate_k<<<ablocks, 256>>>(H, b2, XB, n, 0);
    gemm_tf32_k<<<gblocks, 256, GEMM_SMEM>>>(XB, W3, H, n);
    aggregate_k<<<ablocks, 256>>>(H, b3, XA, n, 1);  // XA = gcn, pool fused

    int halfblocks = (n / 4 + 255) / 256;       // 98
    gemv_heads_k<<<2 * halfblocks, 256>>>(n1W, n1b, g1, n2W, n2b, n, halfblocks,
                                          1.0f / (float)n);
    merge_k<<<1, 128>>>(0, halfblocks);
    conn_k<<<eblocks, 256>>>(srcp, dstp, E);

    int WB = (n + 1023) / 1024;                  // 98
    fused_a_k<<<2 * WB, 256>>>(g2, out, n, WB);
    merge_k<<<1, 128>>>(1, WB);
    fused_b_k<<<WB + 1, 256>>>(XA, eW, eb, ge, out, n);
}

// round 6
// speedup vs baseline: 1.4260x; 1.1834x over previous
#include <cuda_runtime.h>
#include <cuda_bf16.h>
#include <cuda_fp16.h>

#define NMAX 100000
#define EMAX 1600000
#define MASKV (-1000000000.0f)
#define INV_TAU 2.0f

// ---------------- device scratch (static allocation only) ----------------
struct Scr {
    float poolsum[128];
    unsigned int poolmax[128];
    float zmax[2];
    float S[2];
    int isel[2];
};

__device__ __half d_H [NMAX * 128];   // fp16 pre-aggregation activations
__device__ float  d_XA[NMAX * 128];
__device__ float  d_XB[NMAX * 128];
__device__ int    d_counts[NMAX];
__device__ int    d_rowstart[NMAX + 1];
__device__ int    d_cursor[NMAX];
__device__ int    d_csr[EMAX];
__device__ float  d_dinv[NMAX];
__device__ float  d_z1[NMAX];
__device__ float  d_l2[NMAX];
__device__ float  d_z2[NMAX];
__device__ unsigned char d_conn[NMAX];
__device__ int    d_bsum[128];
__device__ int    d_boff[128];
__device__ float  d_bm[2][128];
__device__ float  d_bs[2][128];
__device__ unsigned long long d_bk[2][128];
__device__ Scr    d_scr;

// ---------------- CSR build ----------------
__global__ void degcount_k(const int* __restrict__ dstp, int E) {
    int e = blockIdx.x * blockDim.x + threadIdx.x;
    if (e < E) atomicAdd(&d_counts[dstp[e]], 1);
}

__global__ void scan1_k(int n) {
    __shared__ int sm[1024];
    int t = threadIdx.x;
    int i = blockIdx.x * 1024 + t;
    int v = (i < n) ? d_counts[i] : 0;
    sm[t] = v;
    __syncthreads();
    for (int s = 512; s > 0; s >>= 1) {
        if (t < s) sm[t] += sm[t + s];
        __syncthreads();
    }
    if (t == 0) d_bsum[blockIdx.x] = sm[0];
}

__global__ void scan2_k(int nb, int n) {
    __shared__ int sm[128];
    int t = threadIdx.x;
    int v = (t < nb) ? d_bsum[t] : 0;
    sm[t] = v;
    __syncthreads();
    for (int d = 1; d < 128; d <<= 1) {
        int add = (t >= d) ? sm[t - d] : 0;
        __syncthreads();
        sm[t] += add;
        __syncthreads();
    }
    if (t < nb) d_boff[t] = sm[t] - v;
    if (t == nb - 1) d_rowstart[n] = sm[t];
}

__global__ void scan3_k(int n) {
    __shared__ int sm[1024];
    int t = threadIdx.x;
    int i = blockIdx.x * 1024 + t;
    int v = (i < n) ? d_counts[i] : 0;
    sm[t] = v;
    __syncthreads();
    for (int d = 1; d < 1024; d <<= 1) {
        int add = (t >= d) ? sm[t - d] : 0;
        __syncthreads();
        sm[t] += add;
        __syncthreads();
    }
    if (i < n) {
        int excl = sm[t] - v + d_boff[blockIdx.x];
        d_rowstart[i] = excl;
        d_cursor[i]   = excl;
        d_dinv[i]     = rsqrtf((float)v + 1.0f);
    }
}

__global__ void fill_csr_k(const int* __restrict__ srcp, const int* __restrict__ dstp, int E) {
    int e = blockIdx.x * blockDim.x + threadIdx.x;
    if (e < E) {
        int d = dstp[e];
        int pos = atomicAdd(&d_cursor[d], 1);
        d_csr[pos] = srcp[e];
    }
}

// ---------------- 3xTF32 tensor-core GEMM, smem hi/lo, chunk prefetch ------
// Hout[i,:] = fp16( dinv[i] * (X @ W)[i,:] )
#define XH_ST 68
#define WH_ST 136

__device__ __forceinline__ unsigned f2tf32(float f) {
    unsigned r;
    asm("cvt.rna.tf32.f32 %0, %1;" : "=r"(r) : "f"(f));
    return r;
}

__device__ __forceinline__ void mma_tf32(float* d,
                                         unsigned a0, unsigned a1, unsigned a2, unsigned a3,
                                         unsigned b0, unsigned b1) {
    asm volatile("mma.sync.aligned.m16n8k8.row.col.f32.tf32.tf32.f32 "
                 "{%0,%1,%2,%3}, {%4,%5,%6,%7}, {%8,%9}, {%0,%1,%2,%3};"
                 : "+f"(d[0]), "+f"(d[1]), "+f"(d[2]), "+f"(d[3])
                 : "r"(a0), "r"(a1), "r"(a2), "r"(a3), "r"(b0), "r"(b1));
}

__device__ __forceinline__ void split4(float4 v, float4& hi, float4& lo) {
    hi.x = __uint_as_float(f2tf32(v.x)); lo.x = __uint_as_float(f2tf32(v.x - hi.x));
    hi.y = __uint_as_float(f2tf32(v.y)); lo.y = __uint_as_float(f2tf32(v.y - hi.y));
    hi.z = __uint_as_float(f2tf32(v.z)); lo.z = __uint_as_float(f2tf32(v.z - hi.z));
    hi.w = __uint_as_float(f2tf32(v.w)); lo.w = __uint_as_float(f2tf32(v.w - hi.w));
}

__device__ __forceinline__ void compute_chunk(const float* xh, const float* xl,
                                              const float* wh, const float* wl,
                                              float acc[2][4][4],
                                              int m0, int n0, int r, int c) {
#pragma unroll
    for (int kk = 0; kk < 64; kk += 8) {
        unsigned ah[2][4], al[2][4];
#pragma unroll
        for (int mi = 0; mi < 2; mi++) {
            const float* xb  = xh + (m0 + mi * 16 + r) * XH_ST + c + kk;
            const float* xlb = xl + (m0 + mi * 16 + r) * XH_ST + c + kk;
            ah[mi][0] = __float_as_uint(xb[0]);
            ah[mi][1] = __float_as_uint(xb[8 * XH_ST]);
            ah[mi][2] = __float_as_uint(xb[4]);
            ah[mi][3] = __float_as_uint(xb[8 * XH_ST + 4]);
            al[mi][0] = __float_as_uint(xlb[0]);
            al[mi][1] = __float_as_uint(xlb[8 * XH_ST]);
            al[mi][2] = __float_as_uint(xlb[4]);
            al[mi][3] = __float_as_uint(xlb[8 * XH_ST + 4]);
        }
#pragma unroll
        for (int nj = 0; nj < 4; nj++) {
            const float* wb  = wh + (kk + c) * WH_ST + n0 + nj * 8 + r;
            const float* wlb = wl + (kk + c) * WH_ST + n0 + nj * 8 + r;
            unsigned bh0 = __float_as_uint(wb[0]);
            unsigned bh1 = __float_as_uint(wb[4 * WH_ST]);
            unsigned bl0 = __float_as_uint(wlb[0]);
            unsigned bl1 = __float_as_uint(wlb[4 * WH_ST]);
#pragma unroll
            for (int mi = 0; mi < 2; mi++) {
                mma_tf32(acc[mi][nj], ah[mi][0], ah[mi][1], ah[mi][2], ah[mi][3], bh0, bh1);
                mma_tf32(acc[mi][nj], al[mi][0], al[mi][1], al[mi][2], al[mi][3], bh0, bh1);
                mma_tf32(acc[mi][nj], ah[mi][0], ah[mi][1], ah[mi][2], ah[mi][3], bl0, bl1);
            }
        }
    }
}

__global__ __launch_bounds__(256, 2) void gemm_tf32_k(const float* __restrict__ X,
                                                      const float* __restrict__ W,
                                                      __half* __restrict__ Hout, int n) {
    extern __shared__ float sh[];
    float* xh = sh;                         // 64 x XH_ST
    float* xl = xh + 64 * XH_ST;
    float* wh = xl + 64 * XH_ST;            // 64 x WH_ST
    float* wl = wh + 64 * WH_ST;

    int t = threadIdx.x;
    int row0 = blockIdx.x * 64;
    int nr = n - row0; if (nr > 64) nr = 64;

    int lane = t & 31, wid = t >> 5;
    int wm = wid & 1, wn = wid >> 1;
    int m0 = wm * 32, n0 = wn * 32;
    int r = lane >> 2, c = lane & 3;

    float acc[2][4][4];
#pragma unroll
    for (int mi = 0; mi < 2; mi++)
#pragma unroll
        for (int nj = 0; nj < 4; nj++)
#pragma unroll
            for (int q = 0; q < 4; q++) acc[mi][nj][q] = 0.f;

    // chunk 0 loads -> smem (split hi/lo)
    for (int i = t; i < 2048; i += 256) {
        int k = i >> 5, c4 = i & 31;
        float4 v = *(const float4*)(W + (size_t)k * 128 + c4 * 4);
        float4 hi, lo; split4(v, hi, lo);
        *(float4*)(wh + k * WH_ST + c4 * 4) = hi;
        *(float4*)(wl + k * WH_ST + c4 * 4) = lo;
    }
    for (int i = t; i < nr * 16; i += 256) {
        int rr = i >> 4, c4 = i & 15;
        float4 v = *(const float4*)(X + (size_t)(row0 + rr) * 128 + c4 * 4);
        float4 hi, lo; split4(v, hi, lo);
        *(float4*)(xh + rr * XH_ST + c4 * 4) = hi;
        *(float4*)(xl + rr * XH_ST + c4 * 4) = lo;
    }
    __syncthreads();

    // prefetch chunk 1 into registers
    float4 wreg[8], xreg[4];
#pragma unroll
    for (int u = 0; u < 8; u++) {
        int i = t + u * 256;
        int k = i >> 5, c4 = i & 31;
        wreg[u] = *(const float4*)(W + (size_t)(64 + k) * 128 + c4 * 4);
    }
#pragma unroll
    for (int u = 0; u < 4; u++) {
        int i = t + u * 256;
        if (i < nr * 16) {
            int rr = i >> 4, c4 = i & 15;
            xreg[u] = *(const float4*)(X + (size_t)(row0 + rr) * 128 + 64 + c4 * 4);
        }
    }

    compute_chunk(xh, xl, wh, wl, acc, m0, n0, r, c);
    __syncthreads();

#pragma unroll
    for (int u = 0; u < 8; u++) {
        int i = t + u * 256;
        int k = i >> 5, c4 = i & 31;
        float4 hi, lo; split4(wreg[u], hi, lo);
        *(float4*)(wh + k * WH_ST + c4 * 4) = hi;
        *(float4*)(wl + k * WH_ST + c4 * 4) = lo;
    }
#pragma unroll
    for (int u = 0; u < 4; u++) {
        int i = t + u * 256;
        if (i < nr * 16) {
            int rr = i >> 4, c4 = i & 15;
            float4 hi, lo; split4(xreg[u], hi, lo);
            *(float4*)(xh + rr * XH_ST + c4 * 4) = hi;
            *(float4*)(xl + rr * XH_ST + c4 * 4) = lo;
        }
    }
    __syncthreads();

    compute_chunk(xh, xl, wh, wl, acc, m0, n0, r, c);

#pragma unroll
    for (int mi = 0; mi < 2; mi++) {
        int rloc = m0 + mi * 16 + r;
        float s0 = 0.f, s1 = 0.f;
        if (rloc < nr)     s0 = d_dinv[row0 + rloc];
        if (rloc + 8 < nr) s1 = d_dinv[row0 + rloc + 8];
#pragma unroll
        for (int nj = 0; nj < 4; nj++) {
            int col = n0 + nj * 8 + 2 * c;
            if (rloc < nr)
                *(__half2*)(Hout + (size_t)(row0 + rloc) * 128 + col)
                    = __floats2half2_rn(acc[mi][nj][0] * s0, acc[mi][nj][1] * s0);
            if (rloc + 8 < nr)
                *(__half2*)(Hout + (size_t)(row0 + rloc + 8) * 128 + col)
                    = __floats2half2_rn(acc[mi][nj][2] * s1, acc[mi][nj][3] * s1);
        }
    }
}

// ---------------- aggregation over fp16 rows (pipelined) + pool fusion -----
// out_i = relu(dinv_i * (sum_{e:dst=i} H'[src] + H'[i]) + b)   (fp32 accum)
__global__ __launch_bounds__(256) void aggregate_k(const __half* __restrict__ H,
                                                   const float* __restrict__ bias,
                                                   float* __restrict__ outp, int n,
                                                   int dopool) {
    __shared__ float pS[8][128];
    __shared__ float pM[8][128];
    int t = threadIdx.x;
    int w = (blockIdx.x * blockDim.x + t) >> 5;
    int lane = t & 31;
    int wid = t >> 5;

    float4 o = make_float4(0.f, 0.f, 0.f, 0.f);
    if (w < n) {
        int beg = d_rowstart[w];
        int end = d_rowstart[w + 1];
        float ax = 0.f, ay = 0.f, az = 0.f, aw = 0.f;
        for (int base = beg; base < end; base += 32) {
            int rem = end - base;
            int cnt = rem < 32 ? rem : 32;
            int idx = (lane < cnt) ? d_csr[base + lane] : 0;
            uint2 h[4];
            int m0 = cnt < 4 ? cnt : 4;
#pragma unroll
            for (int u = 0; u < 4; u++) {
                if (u < m0) {
                    int s = __shfl_sync(0xffffffffu, idx, u);
                    h[u] = *(const uint2*)(H + (size_t)s * 128 + lane * 4);
                }
            }
            for (int j0 = 0; j0 < cnt; j0 += 4) {
                int curm = cnt - j0; if (curm > 4) curm = 4;
                int nxtm = cnt - j0 - 4;
                if (nxtm < 0) nxtm = 0;
                if (nxtm > 4) nxtm = 4;
                uint2 h2[4];
#pragma unroll
                for (int u = 0; u < 4; u++) {
                    if (u < nxtm) {
                        int s = __shfl_sync(0xffffffffu, idx, j0 + 4 + u);
                        h2[u] = *(const uint2*)(H + (size_t)s * 128 + lane * 4);
                    } else {
                        h2[u] = make_uint2(0u, 0u);
                    }
                }
#pragma unroll
                for (int u = 0; u < 4; u++) {
                    if (u < curm) {
                        float2 f01 = __half22float2(*(__half2*)&h[u].x);
                        float2 f23 = __half22float2(*(__half2*)&h[u].y);
                        ax += f01.x; ay += f01.y; az += f23.x; aw += f23.y;
                    }
                }
#pragma unroll
                for (int u = 0; u < 4; u++) h[u] = h2[u];
            }
        }
        uint2 hsu = *(const uint2*)(H + (size_t)w * 128 + lane * 4);
        float2 s01 = __half22float2(*(__half2*)&hsu.x);
        float2 s23 = __half22float2(*(__half2*)&hsu.y);
        ax += s01.x; ay += s01.y; az += s23.x; aw += s23.y;
        float di = d_dinv[w];
        float4 b4 = *(const float4*)(bias + lane * 4);
        o.x = fmaxf(di * ax + b4.x, 0.f);
        o.y = fmaxf(di * ay + b4.y, 0.f);
        o.z = fmaxf(di * az + b4.z, 0.f);
        o.w = fmaxf(di * aw + b4.w, 0.f);
        *(float4*)(outp + (size_t)w * 128 + lane * 4) = o;
    }

    if (dopool) {
        pS[wid][lane * 4 + 0] = o.x; pM[wid][lane * 4 + 0] = o.x;
        pS[wid][lane * 4 + 1] = o.y; pM[wid][lane * 4 + 1] = o.y;
        pS[wid][lane * 4 + 2] = o.z; pM[wid][lane * 4 + 2] = o.z;
        pS[wid][lane * 4 + 3] = o.w; pM[wid][lane * 4 + 3] = o.w;
        __syncthreads();
        if (t < 128) {
            float s = 0.f, mx = 0.f;
#pragma unroll
            for (int u = 0; u < 8; u++) { s += pS[u][t]; mx = fmaxf(mx, pM[u][t]); }
            atomicAdd(&d_scr.poolsum[t], s);
            atomicMax(&d_scr.poolmax[t], __float_as_uint(mx));
        }
    }
}

// ---------------- argmax key helpers ----------------
__device__ __forceinline__ unsigned enc_f(float f) {
    unsigned u = __float_as_uint(f);
    return (u & 0x80000000u) ? ~u : (u | 0x80000000u);
}
__device__ __forceinline__ unsigned long long mkkey(float f, int j) {
    return ((unsigned long long)enc_f(f) << 32) | (unsigned long long)(0xFFFFFFFFu - (unsigned)j);
}

// ---------------- head GEMVs + inline pool final + z1 block stats ----------
__global__ __launch_bounds__(256) void gemv_heads_k(const float* __restrict__ n1W,
                                                    const float* __restrict__ n1b,
                                                    const float* __restrict__ g1,
                                                    const float* __restrict__ n2W,
                                                    const float* __restrict__ n2b,
                                                    int ncols, int halfblocks, float inv_n) {
    __shared__ float p[256];
    __shared__ float red[256];
    __shared__ unsigned long long redk[256];
    int t = threadIdx.x;
    if (t < 128) p[t] = d_scr.poolsum[t] * inv_n;
    else         p[t] = __uint_as_float(d_scr.poolmax[t - 128]);
    __syncthreads();
    int second = blockIdx.x >= halfblocks;
    int b = second ? blockIdx.x - halfblocks : blockIdx.x;
    int j4 = b * blockDim.x + t;
    bool valid = (j4 * 4 < ncols);
    float ax = 0.f, ay = 0.f, az = 0.f, aw = 0.f;
    if (valid) {
        const float* W = second ? n2W : n1W;
#pragma unroll 4
        for (int k = 0; k < 256; k++) {
            float4 w4 = *(const float4*)(W + (size_t)k * ncols + j4 * 4);
            float pv = p[k];
            ax += pv * w4.x; ay += pv * w4.y; az += pv * w4.z; aw += pv * w4.w;
        }
    }
    int j = j4 * 4;
    if (!second) {
        float4 o = make_float4(0.f, 0.f, 0.f, 0.f);
        if (valid) {
            float4 bb = *(const float4*)(n1b + j);
            float4 gg = *(const float4*)(g1 + j);
            o.x = (ax + bb.x + gg.x) * INV_TAU;
            o.y = (ay + bb.y + gg.y) * INV_TAU;
            o.z = (az + bb.z + gg.z) * INV_TAU;
            o.w = (aw + bb.w + gg.w) * INV_TAU;
            *(float4*)(d_z1 + j) = o;
        }
        float lm = valid ? fmaxf(fmaxf(o.x, o.y), fmaxf(o.z, o.w)) : -1e30f;
        red[t] = lm;
        __syncthreads();
        for (int s = 128; s > 0; s >>= 1) {
            if (t < s) red[t] = fmaxf(red[t], red[t + s]);
            __syncthreads();
        }
        float bm = red[0];
        __syncthreads();
        float ls = 0.f;
        if (valid) {
            ls = expf(o.x - bm) + expf(o.y - bm) + expf(o.z - bm) + expf(o.w - bm);
        }
        red[t] = ls;
        unsigned long long key = 0ull;
        if (valid) {
            key = mkkey(o.x, j);
            unsigned long long k1 = mkkey(o.y, j + 1); if (k1 > key) key = k1;
            unsigned long long k2 = mkkey(o.z, j + 2); if (k2 > key) key = k2;
            unsigned long long k3 = mkkey(o.w, j + 3); if (k3 > key) key = k3;
        }
        redk[t] = key;
        __syncthreads();
        for (int s = 128; s > 0; s >>= 1) {
            if (t < s) {
                red[t] += red[t + s];
                if (redk[t + s] > redk[t]) redk[t] = redk[t + s];
            }
            __syncthreads();
        }
        if (t == 0) {
            d_bm[0][b] = bm;
            d_bs[0][b] = red[0];
            d_bk[0][b] = redk[0];
        }
    } else {
        if (valid) {
            float4 bb = *(const float4*)(n2b + j);
            float4 o;
            o.x = ax + bb.x; o.y = ay + bb.y; o.z = az + bb.z; o.w = aw + bb.w;
            *(float4*)(d_l2 + j) = o;
        }
    }
}

// ---------------- merge block stats -> global M, S, argmax ----------------
__global__ void merge_k(int which, int nb) {
    __shared__ float sm[128];
    __shared__ float ss[128];
    __shared__ unsigned long long sk[128];
    int t = threadIdx.x;  // 128
    float m = (t < nb) ? d_bm[which][t] : -1e30f;
    sm[t] = m;
    __syncthreads();
    for (int s = 64; s > 0; s >>= 1) {
        if (t < s) sm[t] = fmaxf(sm[t], sm[t + s]);
        __syncthreads();
    }
    float M = sm[0];
    __syncthreads();
    float ls = (t < nb) ? d_bs[which][t] * expf(d_bm[which][t] - M) : 0.f;
    ss[t] = ls;
    sk[t] = (t < nb) ? d_bk[which][t] : 0ull;
    __syncthreads();
    for (int s = 64; s > 0; s >>= 1) {
        if (t < s) {
            ss[t] += ss[t + s];
            if (sk[t + s] > sk[t]) sk[t] = sk[t + s];
        }
        __syncthreads();
    }
    if (t == 0) {
        d_scr.zmax[which] = M;
        d_scr.S[which] = ss[0];
        int idx = (int)(0xFFFFFFFFu - (unsigned)(sk[0] & 0xFFFFFFFFull));
        d_scr.isel[which] = idx;
        if (which == 0) d_conn[idx] = 1;
    }
}

// ---------------- mask of nodes connected to i1 ----------------
__global__ void conn_k(const int* __restrict__ srcp, const int* __restrict__ dstp, int E) {
    int i1 = d_scr.isel[0];
    int e = blockIdx.x * blockDim.x + threadIdx.x;
    if (e < E) {
        int s = srcp[e], d = dstp[e];
        if (s == i1 || d == i1) { d_conn[s] = 1; d_conn[d] = 1; }
    }
}

// ---------------- fused A: [write n1_soft] || [z2 compute + block stats] ----
__global__ __launch_bounds__(256) void fused_a_k(const float* __restrict__ g2,
                                                 float* __restrict__ outp, int n, int WB) {
    __shared__ float red[256];
    __shared__ unsigned long long redk[256];
    int t = threadIdx.x;
    if ((int)blockIdx.x < WB) {
        float M = d_scr.zmax[0];
        float invS = 1.0f / d_scr.S[0];
        int j4 = blockIdx.x * 256 + t;
        int j = j4 * 4;
        if (j < n) {
            float4 z = *(const float4*)(d_z1 + j);
            float4 o;
            o.x = expf(z.x - M) * invS;
            o.y = expf(z.y - M) * invS;
            o.z = expf(z.z - M) * invS;
            o.w = expf(z.w - M) * invS;
            *(float4*)(outp + j) = o;
        }
        return;
    }
    int b = blockIdx.x - WB;
    int j4 = b * 256 + t;
    int j = j4 * 4;
    bool valid = (j < n);
    float4 z = make_float4(0.f, 0.f, 0.f, 0.f);
    if (valid) {
        float4 l = *(const float4*)(d_l2 + j);
        uchar4 cn = *(const uchar4*)(d_conn + j);
        float4 g = *(const float4*)(g2 + j);
        z.x = ((cn.x ? MASKV : l.x) + g.x) * INV_TAU;
        z.y = ((cn.y ? MASKV : l.y) + g.y) * INV_TAU;
        z.z = ((cn.z ? MASKV : l.z) + g.z) * INV_TAU;
        z.w = ((cn.w ? MASKV : l.w) + g.w) * INV_TAU;
        *(float4*)(d_z2 + j) = z;
    }
    float lm = valid ? fmaxf(fmaxf(z.x, z.y), fmaxf(z.z, z.w)) : -1e30f;
    red[t] = lm;
    __syncthreads();
    for (int s = 128; s > 0; s >>= 1) {
        if (t < s) red[t] = fmaxf(red[t], red[t + s]);
        __syncthreads();
    }
    float bm = red[0];
    __syncthreads();
    float ls = 0.f;
    if (valid) ls = expf(z.x - bm) + expf(z.y - bm) + expf(z.z - bm) + expf(z.w - bm);
    red[t] = ls;
    unsigned long long key = 0ull;
    if (valid) {
        key = mkkey(z.x, j);
        unsigned long long k1 = mkkey(z.y, j + 1); if (k1 > key) key = k1;
        unsigned long long k2 = mkkey(z.z, j + 2); if (k2 > key) key = k2;
        unsigned long long k3 = mkkey(z.w, j + 3); if (k3 > key) key = k3;
    }
    redk[t] = key;
    __syncthreads();
    for (int s = 128; s > 0; s >>= 1) {
        if (t < s) {
            red[t] += red[t + s];
            if (redk[t + s] > redk[t]) redk[t] = redk[t + s];
        }
        __syncthreads();
    }
    if (t == 0) {
        d_bm[1][b] = bm;
        d_bs[1][b] = red[0];
        d_bk[1][b] = redk[0];
    }
}

// ---------------- fused B: [esoft] || [write n2_soft] ----------------
__global__ __launch_bounds__(256) void fused_b_k(const float* __restrict__ G,
                                                 const float* __restrict__ eW,
                                                 const float* __restrict__ eb,
                                                 const float* __restrict__ ge,
                                                 float* __restrict__ outp, int n) {
    int t = threadIdx.x;
    if (blockIdx.x == 0) {
        __shared__ float red3[3][128];
        int i1 = d_scr.isel[0];
        int i2 = d_scr.isel[1];
        if (t < 128) {
            float a = G[(size_t)i1 * 128 + t];
            float b = G[(size_t)i2 * 128 + t];
#pragma unroll
            for (int o = 0; o < 3; o++)
                red3[o][t] = a * eW[t * 3 + o] + b * eW[(128 + t) * 3 + o];
        }
        __syncthreads();
        for (int s = 64; s > 0; s >>= 1) {
            if (t < s) {
                red3[0][t] += red3[0][t + s];
                red3[1][t] += red3[1][t + s];
                red3[2][t] += red3[2][t + s];
            }
            __syncthreads();
        }
        if (t == 0) {
            float z0 = (red3[0][0] + eb[0] + ge[0]) * INV_TAU;
            float z1v = (red3[1][0] + eb[1] + ge[1]) * INV_TAU;
            float z2v = (red3[2][0] + eb[2] + ge[2]) * INV_TAU;
            float m = fmaxf(z0, fmaxf(z1v, z2v));
            float e0 = expf(z0 - m), e1 = expf(z1v - m), e2 = expf(z2v - m);
            float inv = 1.0f / (e0 + e1 + e2);
            outp[2 * n + 0] = e0 * inv;
            outp[2 * n + 1] = e1 * inv;
            outp[2 * n + 2] = e2 * inv;
            outp[2 * n + 3] = 1.0f;
        }
        return;
    }
    float M = d_scr.zmax[1];
    float invS = 1.0f / d_scr.S[1];
    int j4 = (blockIdx.x - 1) * 256 + t;
    int j = j4 * 4;
    if (j < n) {
        float4 z = *(const float4*)(d_z2 + j);
        float4 o;
        o.x = expf(z.x - M) * invS;
        o.y = expf(z.y - M) * invS;
        o.z = expf(z.z - M) * invS;
        o.w = expf(z.w - M) * invS;
        *(float4*)(outp + n + j) = o;
    }
}

// ---------------- launcher ----------------
extern "C" void kernel_launch(void* const* d_in, const int* in_sizes, int n_in,
                              void* d_out, int out_size) {
    const float* x   = (const float*)d_in[0];
    const int*   ei  = (const int*)  d_in[1];
    const float* W1  = (const float*)d_in[2];
    const float* b1  = (const float*)d_in[3];
    const float* W2  = (const float*)d_in[4];
    const float* b2  = (const float*)d_in[5];
    const float* W3  = (const float*)d_in[6];
    const float* b3  = (const float*)d_in[7];
    const float* n1W = (const float*)d_in[8];
    const float* n1b = (const float*)d_in[9];
    const float* n2W = (const float*)d_in[10];
    const float* n2b = (const float*)d_in[11];
    const float* eW  = (const float*)d_in[12];
    const float* eb  = (const float*)d_in[13];
    const float* g1  = (const float*)d_in[16];
    const float* g2  = (const float*)d_in[17];
    const float* ge  = (const float*)d_in[18];
    float* out = (float*)d_out;

    int n = in_sizes[0] / 128;
    int E = in_sizes[1] / 2;
    const int* srcp = ei;
    const int* dstp = ei + E;

    void *pc, *pconn, *pscr, *pH, *pXA, *pXB;
    cudaGetSymbolAddress(&pc,    d_counts);
    cudaGetSymbolAddress(&pconn, d_conn);
    cudaGetSymbolAddress(&pscr,  d_scr);
    cudaGetSymbolAddress(&pH,    d_H);
    cudaGetSymbolAddress(&pXA,   d_XA);
    cudaGetSymbolAddress(&pXB,   d_XB);
    __half* H = (__half*)pH;
    float* XA = (float*)pXA;
    float* XB = (float*)pXB;

    const int GEMM_SMEM = (2 * 64 * XH_ST + 2 * 64 * WH_ST) * 4;  // 104448 B
    cudaFuncSetAttribute(gemm_tf32_k, cudaFuncAttributeMaxDynamicSharedMemorySize, GEMM_SMEM);

    cudaMemsetAsync(pc,    0, (size_t)n * sizeof(int), 0);
    cudaMemsetAsync(pconn, 0, (size_t)n, 0);
    cudaMemsetAsync(pscr,  0, sizeof(Scr), 0);

    int eblocks = (E + 255) / 256;
    int nb = (n + 1023) / 1024;
    degcount_k<<<eblocks, 256>>>(dstp, E);
    scan1_k<<<nb, 1024>>>(n);
    scan2_k<<<1, 128>>>(nb, n);
    scan3_k<<<nb, 1024>>>(n);
    fill_csr_k<<<eblocks, 256>>>(srcp, dstp, E);

    int gblocks = (n + 63) / 64;
    int ablocks = (n + 7) / 8;

    gemm_tf32_k<<<gblocks, 256, GEMM_SMEM>>>(x,  W1, H, n);
    aggregate_k<<<ablocks, 256>>>(H, b1, XA, n, 0);
    gemm_tf32_k<<<gblocks, 256, GEMM_SMEM>>>(XA, W2, H, n);
    aggregate_k<<<ablocks, 256>>>(H, b2, XB, n, 0);
    gemm_tf32_k<<<gblocks, 256, GEMM_SMEM>>>(XB, W3, H, n);
    aggregate_k<<<ablocks, 256>>>(H, b3, XA, n, 1);  // XA = gcn, pool fused

    int halfblocks = (n / 4 + 255) / 256;       // 98
    gemv_heads_k<<<2 * halfblocks, 256>>>(n1W, n1b, g1, n2W, n2b, n, halfblocks,
                                          1.0f / (float)n);
    merge_k<<<1, 128>>>(0, halfblocks);
    conn_k<<<eblocks, 256>>>(srcp, dstp, E);

    int WB = (n + 1023) / 1024;                  // 98
    fused_a_k<<<2 * WB, 256>>>(g2, out, n, WB);
    merge_k<<<1, 128>>>(1, WB);
    fused_b_k<<<WB + 1, 256>>>(XA, eW, eb, ge, out, n);
}

// round 7
// speedup vs baseline: 1.7659x; 1.2384x over previous
#include <cuda_runtime.h>
#include <cuda_bf16.h>
#include <cuda_fp16.h>

#define NMAX 100000
#define EMAX 1600000
#define MASKV (-1000000000.0f)
#define INV_TAU 2.0f

// ---------------- device scratch (static allocation only) ----------------
struct Scr {
    float poolsum[128];
    unsigned int poolmax[128];
    float zmax[2];
    float S[2];
    int isel[2];
};

__device__ __half d_H[NMAX * 128];   // GEMM output (pre-aggregation)
__device__ __half d_P[NMAX * 128];   // activation ping
__device__ __half d_Q[NMAX * 128];   // activation pong
__device__ int    d_counts[NMAX];
__device__ int    d_rowstart[NMAX + 1];
__device__ int    d_cursor[NMAX];
__device__ int    d_csr[EMAX];
__device__ float  d_dinv[NMAX];
__device__ float  d_z1[NMAX];
__device__ float  d_l2[NMAX];
__device__ float  d_z2[NMAX];
__device__ unsigned char d_conn[NMAX];
__device__ int    d_bsum[128];
__device__ int    d_boff[128];
__device__ float  d_bm[2][128];
__device__ float  d_bs[2][128];
__device__ unsigned long long d_bk[2][128];
__device__ Scr    d_scr;

// ---------------- CSR build ----------------
__global__ void degcount_k(const int* __restrict__ dstp, int E) {
    int e = blockIdx.x * blockDim.x + threadIdx.x;
    if (e < E) atomicAdd(&d_counts[dstp[e]], 1);
}

__global__ void scan1_k(int n) {
    __shared__ int sm[1024];
    int t = threadIdx.x;
    int i = blockIdx.x * 1024 + t;
    int v = (i < n) ? d_counts[i] : 0;
    sm[t] = v;
    __syncthreads();
    for (int s = 512; s > 0; s >>= 1) {
        if (t < s) sm[t] += sm[t + s];
        __syncthreads();
    }
    if (t == 0) d_bsum[blockIdx.x] = sm[0];
}

__global__ void scan2_k(int nb, int n) {
    __shared__ int sm[128];
    int t = threadIdx.x;
    int v = (t < nb) ? d_bsum[t] : 0;
    sm[t] = v;
    __syncthreads();
    for (int d = 1; d < 128; d <<= 1) {
        int add = (t >= d) ? sm[t - d] : 0;
        __syncthreads();
        sm[t] += add;
        __syncthreads();
    }
    if (t < nb) d_boff[t] = sm[t] - v;
    if (t == nb - 1) d_rowstart[n] = sm[t];
}

__global__ void scan3_k(int n) {
    __shared__ int sm[1024];
    int t = threadIdx.x;
    int i = blockIdx.x * 1024 + t;
    int v = (i < n) ? d_counts[i] : 0;
    sm[t] = v;
    __syncthreads();
    for (int d = 1; d < 1024; d <<= 1) {
        int add = (t >= d) ? sm[t - d] : 0;
        __syncthreads();
        sm[t] += add;
        __syncthreads();
    }
    if (i < n) {
        int excl = sm[t] - v + d_boff[blockIdx.x];
        d_rowstart[i] = excl;
        d_cursor[i]   = excl;
        d_dinv[i]     = rsqrtf((float)v + 1.0f);
    }
}

__global__ void fill_csr_k(const int* __restrict__ srcp, const int* __restrict__ dstp, int E) {
    int e = blockIdx.x * blockDim.x + threadIdx.x;
    if (e < E) {
        int d = dstp[e];
        int pos = atomicAdd(&d_cursor[d], 1);
        d_csr[pos] = srcp[e];
    }
}

// ---------------- x fp32 -> fp16 ----------------
__global__ void cvt_x_k(const float* __restrict__ x, __half* __restrict__ xo, int total4) {
    int i = blockIdx.x * blockDim.x + threadIdx.x;
    if (i < total4) {
        float4 v = *(const float4*)(x + i * 4);
        __half2 a = __floats2half2_rn(v.x, v.y);
        __half2 b = __floats2half2_rn(v.z, v.w);
        *(uint2*)(xo + i * 4) = make_uint2(*(unsigned*)&a, *(unsigned*)&b);
    }
}

// ---------------- fp16 tensor-core GEMM: Hout = fp16(dinv * (X @ W)) ------
// X [n,128] fp16 row-major; W [128,128] fp32 row-major (k,n).
// Block: 64 rows x 128 cols, K=128 in one smem residency.
#define XS_H 136   // halfs per X smem row
#define BS_W 132   // half2 per B smem k2-row

__device__ __forceinline__ void mma_f16(float* d,
                                        unsigned a0, unsigned a1, unsigned a2, unsigned a3,
                                        unsigned b0, unsigned b1) {
    asm volatile("mma.sync.aligned.m16n8k16.row.col.f32.f16.f16.f32 "
                 "{%0,%1,%2,%3}, {%4,%5,%6,%7}, {%8,%9}, {%0,%1,%2,%3};"
                 : "+f"(d[0]), "+f"(d[1]), "+f"(d[2]), "+f"(d[3])
                 : "r"(a0), "r"(a1), "r"(a2), "r"(a3), "r"(b0), "r"(b1));
}

__global__ __launch_bounds__(256) void gemm_f16_k(const __half* __restrict__ X,
                                                  const float* __restrict__ W,
                                                  __half* __restrict__ Hout, int n) {
    extern __shared__ char shraw[];
    __half*  xs = (__half*)shraw;                    // 64 x XS_H halfs
    __half2* bs = (__half2*)(shraw + 64 * XS_H * 2); // 64 x BS_W half2 (k-pairs)

    int t = threadIdx.x;
    int row0 = blockIdx.x * 64;
    int nr = n - row0; if (nr > 64) nr = 64;

    // W: pack k-pairs into half2: bs[k2][n] = (W[2k2][n], W[2k2+1][n])
    for (int i = t; i < 64 * 128; i += 256) {
        int k2 = i >> 7, nn = i & 127;
        float w0 = W[(size_t)(2 * k2) * 128 + nn];
        float w1 = W[(size_t)(2 * k2 + 1) * 128 + nn];
        bs[k2 * BS_W + nn] = __floats2half2_rn(w0, w1);
    }
    // X rows (fp16 copy, 16B chunks)
    for (int i = t; i < nr * 16; i += 256) {
        int rr = i >> 4, c8 = i & 15;
        uint4 v = *(const uint4*)(X + (size_t)(row0 + rr) * 128 + c8 * 8);
        *(uint4*)(xs + rr * XS_H + c8 * 8) = v;
    }
    __syncthreads();

    int lane = t & 31, wid = t >> 5;
    int wm = wid & 1, wn = wid >> 1;     // warp tile 32 rows x 32 cols
    int m0 = wm * 32, n0 = wn * 32;
    int r = lane >> 2, c = lane & 3;

    float acc[2][4][4];
#pragma unroll
    for (int mi = 0; mi < 2; mi++)
#pragma unroll
        for (int nj = 0; nj < 4; nj++)
#pragma unroll
            for (int q = 0; q < 4; q++) acc[mi][nj][q] = 0.f;

#pragma unroll
    for (int k0 = 0; k0 < 8; k0++) {     // k16 steps
        unsigned a[2][4];
#pragma unroll
        for (int mi = 0; mi < 2; mi++) {
            const __half* xb = xs + (m0 + mi * 16 + r) * XS_H + k0 * 16 + 2 * c;
            a[mi][0] = *(const unsigned*)(xb);
            a[mi][1] = *(const unsigned*)(xb + 8 * XS_H);
            a[mi][2] = *(const unsigned*)(xb + 8);
            a[mi][3] = *(const unsigned*)(xb + 8 * XS_H + 8);
        }
#pragma unroll
        for (int nj = 0; nj < 4; nj++) {
            const __half2* bb = bs + (k0 * 8 + c) * BS_W + n0 + nj * 8 + r;
            unsigned b0 = *(const unsigned*)(bb);
            unsigned b1 = *(const unsigned*)(bb + 4 * BS_W);
#pragma unroll
            for (int mi = 0; mi < 2; mi++)
                mma_f16(acc[mi][nj], a[mi][0], a[mi][1], a[mi][2], a[mi][3], b0, b1);
        }
    }

#pragma unroll
    for (int mi = 0; mi < 2; mi++) {
        int rloc = m0 + mi * 16 + r;
        float s0 = 0.f, s1 = 0.f;
        if (rloc < nr)     s0 = d_dinv[row0 + rloc];
        if (rloc + 8 < nr) s1 = d_dinv[row0 + rloc + 8];
#pragma unroll
        for (int nj = 0; nj < 4; nj++) {
            int col = n0 + nj * 8 + 2 * c;
            if (rloc < nr) {
                __half2 h = __floats2half2_rn(acc[mi][nj][0] * s0, acc[mi][nj][1] * s0);
                *(__half2*)(Hout + (size_t)(row0 + rloc) * 128 + col) = h;
            }
            if (rloc + 8 < nr) {
                __half2 h = __floats2half2_rn(acc[mi][nj][2] * s1, acc[mi][nj][3] * s1);
                *(__half2*)(Hout + (size_t)(row0 + rloc + 8) * 128 + col) = h;
            }
        }
    }
}

// ---------------- aggregation over fp16 rows, fp16 output + pool fusion ----
// out_i = fp16( relu(dinv_i * (sum_{e:dst=i} H'[src] + H'[i]) + b) )
__global__ __launch_bounds__(256) void aggregate_k(const __half* __restrict__ H,
                                                   const float* __restrict__ bias,
                                                   __half* __restrict__ outp, int n,
                                                   int dopool) {
    __shared__ float pS[8][128];
    __shared__ float pM[8][128];
    int t = threadIdx.x;
    int w = (blockIdx.x * blockDim.x + t) >> 5;
    int lane = t & 31;
    int wid = t >> 5;

    float4 o = make_float4(0.f, 0.f, 0.f, 0.f);
    if (w < n) {
        int beg = d_rowstart[w];
        int end = d_rowstart[w + 1];
        float ax = 0.f, ay = 0.f, az = 0.f, aw = 0.f;
        for (int base = beg; base < end; base += 32) {
            int rem = end - base;
            int cnt = rem < 32 ? rem : 32;
            int idx = (lane < cnt) ? d_csr[base + lane] : 0;
            uint2 h[4];
            int m0 = cnt < 4 ? cnt : 4;
#pragma unroll
            for (int u = 0; u < 4; u++) {
                if (u < m0) {
                    int s = __shfl_sync(0xffffffffu, idx, u);
                    h[u] = *(const uint2*)(H + (size_t)s * 128 + lane * 4);
                }
            }
            for (int j0 = 0; j0 < cnt; j0 += 4) {
                int curm = cnt - j0; if (curm > 4) curm = 4;
                int nxtm = cnt - j0 - 4;
                if (nxtm < 0) nxtm = 0;
                if (nxtm > 4) nxtm = 4;
                uint2 h2[4];
#pragma unroll
                for (int u = 0; u < 4; u++) {
                    if (u < nxtm) {
                        int s = __shfl_sync(0xffffffffu, idx, j0 + 4 + u);
                        h2[u] = *(const uint2*)(H + (size_t)s * 128 + lane * 4);
                    } else {
                        h2[u] = make_uint2(0u, 0u);
                    }
                }
#pragma unroll
                for (int u = 0; u < 4; u++) {
                    if (u < curm) {
                        float2 f01 = __half22float2(*(__half2*)&h[u].x);
                        float2 f23 = __half22float2(*(__half2*)&h[u].y);
                        ax += f01.x; ay += f01.y; az += f23.x; aw += f23.y;
                    }
                }
#pragma unroll
                for (int u = 0; u < 4; u++) h[u] = h2[u];
            }
        }
        uint2 hsu = *(const uint2*)(H + (size_t)w * 128 + lane * 4);
        float2 s01 = __half22float2(*(__half2*)&hsu.x);
        float2 s23 = __half22float2(*(__half2*)&hsu.y);
        ax += s01.x; ay += s01.y; az += s23.x; aw += s23.y;
        float di = d_dinv[w];
        float4 b4 = *(const float4*)(bias + lane * 4);
        o.x = fmaxf(di * ax + b4.x, 0.f);
        o.y = fmaxf(di * ay + b4.y, 0.f);
        o.z = fmaxf(di * az + b4.z, 0.f);
        o.w = fmaxf(di * aw + b4.w, 0.f);
        __half2 o01 = __floats2half2_rn(o.x, o.y);
        __half2 o23 = __floats2half2_rn(o.z, o.w);
        *(uint2*)(outp + (size_t)w * 128 + lane * 4)
            = make_uint2(*(unsigned*)&o01, *(unsigned*)&o23);
    }

    if (dopool) {
        pS[wid][lane * 4 + 0] = o.x; pM[wid][lane * 4 + 0] = o.x;
        pS[wid][lane * 4 + 1] = o.y; pM[wid][lane * 4 + 1] = o.y;
        pS[wid][lane * 4 + 2] = o.z; pM[wid][lane * 4 + 2] = o.z;
        pS[wid][lane * 4 + 3] = o.w; pM[wid][lane * 4 + 3] = o.w;
        __syncthreads();
        if (t < 128) {
            float s = 0.f, mx = 0.f;
#pragma unroll
            for (int u = 0; u < 8; u++) { s += pS[u][t]; mx = fmaxf(mx, pM[u][t]); }
            atomicAdd(&d_scr.poolsum[t], s);
            atomicMax(&d_scr.poolmax[t], __float_as_uint(mx));
        }
    }
}

// ---------------- argmax key helpers ----------------
__device__ __forceinline__ unsigned enc_f(float f) {
    unsigned u = __float_as_uint(f);
    return (u & 0x80000000u) ? ~u : (u | 0x80000000u);
}
__device__ __forceinline__ unsigned long long mkkey(float f, int j) {
    return ((unsigned long long)enc_f(f) << 32) | (unsigned long long)(0xFFFFFFFFu - (unsigned)j);
}

// ---------------- head GEMVs + inline pool final + z1 block stats ----------
__global__ __launch_bounds__(256) void gemv_heads_k(const float* __restrict__ n1W,
                                                    const float* __restrict__ n1b,
                                                    const float* __restrict__ g1,
                                                    const float* __restrict__ n2W,
                                                    const float* __restrict__ n2b,
                                                    int ncols, int halfblocks, float inv_n) {
    __shared__ float p[256];
    __shared__ float red[256];
    __shared__ unsigned long long redk[256];
    int t = threadIdx.x;
    if (t < 128) p[t] = d_scr.poolsum[t] * inv_n;
    else         p[t] = __uint_as_float(d_scr.poolmax[t - 128]);
    __syncthreads();
    int second = blockIdx.x >= halfblocks;
    int b = second ? blockIdx.x - halfblocks : blockIdx.x;
    int j4 = b * blockDim.x + t;
    bool valid = (j4 * 4 < ncols);
    float ax = 0.f, ay = 0.f, az = 0.f, aw = 0.f;
    if (valid) {
        const float* W = second ? n2W : n1W;
#pragma unroll 4
        for (int k = 0; k < 256; k++) {
            float4 w4 = *(const float4*)(W + (size_t)k * ncols + j4 * 4);
            float pv = p[k];
            ax += pv * w4.x; ay += pv * w4.y; az += pv * w4.z; aw += pv * w4.w;
        }
    }
    int j = j4 * 4;
    if (!second) {
        float4 o = make_float4(0.f, 0.f, 0.f, 0.f);
        if (valid) {
            float4 bb = *(const float4*)(n1b + j);
            float4 gg = *(const float4*)(g1 + j);
            o.x = (ax + bb.x + gg.x) * INV_TAU;
            o.y = (ay + bb.y + gg.y) * INV_TAU;
            o.z = (az + bb.z + gg.z) * INV_TAU;
            o.w = (aw + bb.w + gg.w) * INV_TAU;
            *(float4*)(d_z1 + j) = o;
        }
        float lm = valid ? fmaxf(fmaxf(o.x, o.y), fmaxf(o.z, o.w)) : -1e30f;
        red[t] = lm;
        __syncthreads();
        for (int s = 128; s > 0; s >>= 1) {
            if (t < s) red[t] = fmaxf(red[t], red[t + s]);
            __syncthreads();
        }
        float bm = red[0];
        __syncthreads();
        float ls = 0.f;
        if (valid) {
            ls = expf(o.x - bm) + expf(o.y - bm) + expf(o.z - bm) + expf(o.w - bm);
        }
        red[t] = ls;
        unsigned long long key = 0ull;
        if (valid) {
            key = mkkey(o.x, j);
            unsigned long long k1 = mkkey(o.y, j + 1); if (k1 > key) key = k1;
            unsigned long long k2 = mkkey(o.z, j + 2); if (k2 > key) key = k2;
            unsigned long long k3 = mkkey(o.w, j + 3); if (k3 > key) key = k3;
        }
        redk[t] = key;
        __syncthreads();
        for (int s = 128; s > 0; s >>= 1) {
            if (t < s) {
                red[t] += red[t + s];
                if (redk[t + s] > redk[t]) redk[t] = redk[t + s];
            }
            __syncthreads();
        }
        if (t == 0) {
            d_bm[0][b] = bm;
            d_bs[0][b] = red[0];
            d_bk[0][b] = redk[0];
        }
    } else {
        if (valid) {
            float4 bb = *(const float4*)(n2b + j);
            float4 o;
            o.x = ax + bb.x; o.y = ay + bb.y; o.z = az + bb.z; o.w = aw + bb.w;
            *(float4*)(d_l2 + j) = o;
        }
    }
}

// ---------------- merge block stats -> global M, S, argmax ----------------
__global__ void merge_k(int which, int nb) {
    __shared__ float sm[128];
    __shared__ float ss[128];
    __shared__ unsigned long long sk[128];
    int t = threadIdx.x;  // 128
    float m = (t < nb) ? d_bm[which][t] : -1e30f;
    sm[t] = m;
    __syncthreads();
    for (int s = 64; s > 0; s >>= 1) {
        if (t < s) sm[t] = fmaxf(sm[t], sm[t + s]);
        __syncthreads();
    }
    float M = sm[0];
    __syncthreads();
    float ls = (t < nb) ? d_bs[which][t] * expf(d_bm[which][t] - M) : 0.f;
    ss[t] = ls;
    sk[t] = (t < nb) ? d_bk[which][t] : 0ull;
    __syncthreads();
    for (int s = 64; s > 0; s >>= 1) {
        if (t < s) {
            ss[t] += ss[t + s];
            if (sk[t + s] > sk[t]) sk[t] = sk[t + s];
        }
        __syncthreads();
    }
    if (t == 0) {
        d_scr.zmax[which] = M;
        d_scr.S[which] = ss[0];
        int idx = (int)(0xFFFFFFFFu - (unsigned)(sk[0] & 0xFFFFFFFFull));
        d_scr.isel[which] = idx;
        if (which == 0) d_conn[idx] = 1;
    }
}

// ---------------- mask of nodes connected to i1 ----------------
__global__ void conn_k(const int* __restrict__ srcp, const int* __restrict__ dstp, int E) {
    int i1 = d_scr.isel[0];
    int e = blockIdx.x * blockDim.x + threadIdx.x;
    if (e < E) {
        int s = srcp[e], d = dstp[e];
        if (s == i1 || d == i1) { d_conn[s] = 1; d_conn[d] = 1; }
    }
}

// ---------------- fused A: [write n1_soft] || [z2 compute + block stats] ----
__global__ __launch_bounds__(256) void fused_a_k(const float* __restrict__ g2,
                                                 float* __restrict__ outp, int n, int WB) {
    __shared__ float red[256];
    __shared__ unsigned long long redk[256];
    int t = threadIdx.x;
    if ((int)blockIdx.x < WB) {
        float M = d_scr.zmax[0];
        float invS = 1.0f / d_scr.S[0];
        int j4 = blockIdx.x * 256 + t;
        int j = j4 * 4;
        if (j < n) {
            float4 z = *(const float4*)(d_z1 + j);
            float4 o;
            o.x = expf(z.x - M) * invS;
            o.y = expf(z.y - M) * invS;
            o.z = expf(z.z - M) * invS;
            o.w = expf(z.w - M) * invS;
            *(float4*)(outp + j) = o;
        }
        return;
    }
    int b = blockIdx.x - WB;
    int j4 = b * 256 + t;
    int j = j4 * 4;
    bool valid = (j < n);
    float4 z = make_float4(0.f, 0.f, 0.f, 0.f);
    if (valid) {
        float4 l = *(const float4*)(d_l2 + j);
        uchar4 cn = *(const uchar4*)(d_conn + j);
        float4 g = *(const float4*)(g2 + j);
        z.x = ((cn.x ? MASKV : l.x) + g.x) * INV_TAU;
        z.y = ((cn.y ? MASKV : l.y) + g.y) * INV_TAU;
        z.z = ((cn.z ? MASKV : l.z) + g.z) * INV_TAU;
        z.w = ((cn.w ? MASKV : l.w) + g.w) * INV_TAU;
        *(float4*)(d_z2 + j) = z;
    }
    float lm = valid ? fmaxf(fmaxf(z.x, z.y), fmaxf(z.z, z.w)) : -1e30f;
    red[t] = lm;
    __syncthreads();
    for (int s = 128; s > 0; s >>= 1) {
        if (t < s) red[t] = fmaxf(red[t], red[t + s]);
        __syncthreads();
    }
    float bm = red[0];
    __syncthreads();
    float ls = 0.f;
    if (valid) ls = expf(z.x - bm) + expf(z.y - bm) + expf(z.z - bm) + expf(z.w - bm);
    red[t] = ls;
    unsigned long long key = 0ull;
    if (valid) {
        key = mkkey(z.x, j);
        unsigned long long k1 = mkkey(z.y, j + 1); if (k1 > key) key = k1;
        unsigned long long k2 = mkkey(z.z, j + 2); if (k2 > key) key = k2;
        unsigned long long k3 = mkkey(z.w, j + 3); if (k3 > key) key = k3;
    }
    redk[t] = key;
    __syncthreads();
    for (int s = 128; s > 0; s >>= 1) {
        if (t < s) {
            red[t] += red[t + s];
            if (redk[t + s] > redk[t]) redk[t] = redk[t + s];
        }
        __syncthreads();
    }
    if (t == 0) {
        d_bm[1][b] = bm;
        d_bs[1][b] = red[0];
        d_bk[1][b] = redk[0];
    }
}

// ---------------- fused B: [esoft] || [write n2_soft] ----------------
__global__ __launch_bounds__(256) void fused_b_k(const __half* __restrict__ G,
                                                 const float* __restrict__ eW,
                                                 const float* __restrict__ eb,
                                                 const float* __restrict__ ge,
                                                 float* __restrict__ outp, int n) {
    int t = threadIdx.x;
    if (blockIdx.x == 0) {
        __shared__ float red3[3][128];
        int i1 = d_scr.isel[0];
        int i2 = d_scr.isel[1];
        if (t < 128) {
            float a = __half2float(G[(size_t)i1 * 128 + t]);
            float b = __half2float(G[(size_t)i2 * 128 + t]);
#pragma unroll
            for (int o = 0; o < 3; o++)
                red3[o][t] = a * eW[t * 3 + o] + b * eW[(128 + t) * 3 + o];
        }
        __syncthreads();
        for (int s = 64; s > 0; s >>= 1) {
            if (t < s) {
                red3[0][t] += red3[0][t + s];
                red3[1][t] += red3[1][t + s];
                red3[2][t] += red3[2][t + s];
            }
            __syncthreads();
        }
        if (t == 0) {
            float z0 = (red3[0][0] + eb[0] + ge[0]) * INV_TAU;
            float z1v = (red3[1][0] + eb[1] + ge[1]) * INV_TAU;
            float z2v = (red3[2][0] + eb[2] + ge[2]) * INV_TAU;
            float m = fmaxf(z0, fmaxf(z1v, z2v));
            float e0 = expf(z0 - m), e1 = expf(z1v - m), e2 = expf(z2v - m);
            float inv = 1.0f / (e0 + e1 + e2);
            outp[2 * n + 0] = e0 * inv;
            outp[2 * n + 1] = e1 * inv;
            outp[2 * n + 2] = e2 * inv;
            outp[2 * n + 3] = 1.0f;
        }
        return;
    }
    float M = d_scr.zmax[1];
    float invS = 1.0f / d_scr.S[1];
    int j4 = (blockIdx.x - 1) * 256 + t;
    int j = j4 * 4;
    if (j < n) {
        float4 z = *(const float4*)(d_z2 + j);
        float4 o;
        o.x = expf(z.x - M) * invS;
        o.y = expf(z.y - M) * invS;
        o.z = expf(z.z - M) * invS;
        o.w = expf(z.w - M) * invS;
        *(float4*)(outp + n + j) = o;
    }
}

// ---------------- launcher ----------------
extern "C" void kernel_launch(void* const* d_in, const int* in_sizes, int n_in,
                              void* d_out, int out_size) {
    const float* x   = (const float*)d_in[0];
    const int*   ei  = (const int*)  d_in[1];
    const float* W1  = (const float*)d_in[2];
    const float* b1  = (const float*)d_in[3];
    const float* W2  = (const float*)d_in[4];
    const float* b2  = (const float*)d_in[5];
    const float* W3  = (const float*)d_in[6];
    const float* b3  = (const float*)d_in[7];
    const float* n1W = (const float*)d_in[8];
    const float* n1b = (const float*)d_in[9];
    const float* n2W = (const float*)d_in[10];
    const float* n2b = (const float*)d_in[11];
    const float* eW  = (const float*)d_in[12];
    const float* eb  = (const float*)d_in[13];
    const float* g1  = (const float*)d_in[16];
    const float* g2  = (const float*)d_in[17];
    const float* ge  = (const float*)d_in[18];
    float* out = (float*)d_out;

    int n = in_sizes[0] / 128;
    int E = in_sizes[1] / 2;
    const int* srcp = ei;
    const int* dstp = ei + E;

    void *pc, *pconn, *pscr, *pH, *pP, *pQ;
    cudaGetSymbolAddress(&pc,    d_counts);
    cudaGetSymbolAddress(&pconn, d_conn);
    cudaGetSymbolAddress(&pscr,  d_scr);
    cudaGetSymbolAddress(&pH,    d_H);
    cudaGetSymbolAddress(&pP,    d_P);
    cudaGetSymbolAddress(&pQ,    d_Q);
    __half* H = (__half*)pH;
    __half* P = (__half*)pP;
    __half* Q = (__half*)pQ;

    const int GEMM_SMEM = 64 * XS_H * 2 + 64 * BS_W * 4;  // 17408 + 33792 = 51200 B
    cudaFuncSetAttribute(gemm_f16_k, cudaFuncAttributeMaxDynamicSharedMemorySize, GEMM_SMEM);

    cudaMemsetAsync(pc,    0, (size_t)n * sizeof(int), 0);
    cudaMemsetAsync(pconn, 0, (size_t)n, 0);
    cudaMemsetAsync(pscr,  0, sizeof(Scr), 0);

    int eblocks = (E + 255) / 256;
    int nb = (n + 1023) / 1024;
    degcount_k<<<eblocks, 256>>>(dstp, E);
    scan1_k<<<nb, 1024>>>(n);
    scan2_k<<<1, 128>>>(nb, n);
    scan3_k<<<nb, 1024>>>(n);
    fill_csr_k<<<eblocks, 256>>>(srcp, dstp, E);

    int total4 = n * 32;  // n*128/4
    cvt_x_k<<<(total4 + 255) / 256, 256>>>(x, P, total4);

    int gblocks = (n + 63) / 64;
    int ablocks = (n + 7) / 8;

    gemm_f16_k<<<gblocks, 256, GEMM_SMEM>>>(P, W1, H, n);
    aggregate_k<<<ablocks, 256>>>(H, b1, Q, n, 0);
    gemm_f16_k<<<gblocks, 256, GEMM_SMEM>>>(Q, W2, H, n);
    aggregate_k<<<ablocks, 256>>>(H, b2, P, n, 0);
    gemm_f16_k<<<gblocks, 256, GEMM_SMEM>>>(P, W3, H, n);
    aggregate_k<<<ablocks, 256>>>(H, b3, Q, n, 1);  // Q = gcn, pool fused

    int halfblocks = (n / 4 + 255) / 256;       // 98
    gemv_heads_k<<<2 * halfblocks, 256>>>(n1W, n1b, g1, n2W, n2b, n, halfblocks,
                                          1.0f / (float)n);
    merge_k<<<1, 128>>>(0, halfblocks);
    conn_k<<<eblocks, 256>>>(srcp, dstp, E);

    int WB = (n + 1023) / 1024;                  // 98
    fused_a_k<<<2 * WB, 256>>>(g2, out, n, WB);
    merge_k<<<1, 128>>>(1, WB);
    fused_b_k<<<WB + 1, 256>>>(Q, eW, eb, ge, out, n);
}

// round 10
// speedup vs baseline: 1.8477x; 1.0463x over previous
#include <cuda_runtime.h>
#include <cuda_bf16.h>
#include <cuda_fp16.h>

#define NMAX 100000
#define EMAX 1600000
#define MASKV (-1000000000.0f)
#define INV_TAU 2.0f

// ---------------- device scratch (static allocation only) ----------------
struct Scr {
    float poolsum[128];
    unsigned int poolmax[128];
    float zmax[2];
    float S[2];
    int isel[2];
};

__device__ __half d_H[NMAX * 128];   // GEMM output (pre-aggregation)
__device__ __half d_P[NMAX * 128];   // activation ping
__device__ __half d_Q[NMAX * 128];   // activation pong
__device__ int    d_counts[NMAX];
__device__ int    d_rowstart[NMAX + 1];
__device__ int    d_cursor[NMAX];
__device__ int    d_csr[EMAX];
__device__ float  d_dinv[NMAX];
__device__ float  d_z1[NMAX];
__device__ float  d_l2[NMAX];
__device__ float  d_z2[NMAX];
__device__ unsigned char d_conn[NMAX];
__device__ int    d_bsum[128];
__device__ int    d_boff[128];
__device__ float  d_bm[2][128];
__device__ float  d_bs[2][128];
__device__ unsigned long long d_bk[2][128];
__device__ Scr    d_scr;

// ---------------- CSR build ----------------
__global__ void degcount_k(const int* __restrict__ dstp, int E) {
    int e = blockIdx.x * blockDim.x + threadIdx.x;
    if (e < E) atomicAdd(&d_counts[dstp[e]], 1);
}

__global__ void scan1_k(int n) {
    __shared__ int sm[1024];
    int t = threadIdx.x;
    int i = blockIdx.x * 1024 + t;
    int v = (i < n) ? d_counts[i] : 0;
    sm[t] = v;
    __syncthreads();
    for (int s = 512; s > 0; s >>= 1) {
        if (t < s) sm[t] += sm[t + s];
        __syncthreads();
    }
    if (t == 0) d_bsum[blockIdx.x] = sm[0];
}

__global__ void scan2_k(int nb, int n) {
    __shared__ int sm[128];
    int t = threadIdx.x;
    int v = (t < nb) ? d_bsum[t] : 0;
    sm[t] = v;
    __syncthreads();
    for (int d = 1; d < 128; d <<= 1) {
        int add = (t >= d) ? sm[t - d] : 0;
        __syncthreads();
        sm[t] += add;
        __syncthreads();
    }
    if (t < nb) d_boff[t] = sm[t] - v;
    if (t == nb - 1) d_rowstart[n] = sm[t];
}

__global__ void scan3_k(int n) {
    __shared__ int sm[1024];
    int t = threadIdx.x;
    int i = blockIdx.x * 1024 + t;
    int v = (i < n) ? d_counts[i] : 0;
    sm[t] = v;
    __syncthreads();
    for (int d = 1; d < 1024; d <<= 1) {
        int add = (t >= d) ? sm[t - d] : 0;
        __syncthreads();
        sm[t] += add;
        __syncthreads();
    }
    if (i < n) {
        int excl = sm[t] - v + d_boff[blockIdx.x];
        d_rowstart[i] = excl;
        d_cursor[i]   = excl;
        d_dinv[i]     = rsqrtf((float)v + 1.0f);
    }
}

__global__ void fill_csr_k(const int* __restrict__ srcp, const int* __restrict__ dstp, int E) {
    int e = blockIdx.x * blockDim.x + threadIdx.x;
    if (e < E) {
        int d = dstp[e];
        int pos = atomicAdd(&d_cursor[d], 1);
        d_csr[pos] = srcp[e];
    }
}

// ---------------- x fp32 -> fp16 ----------------
__global__ void cvt_x_k(const float* __restrict__ x, __half* __restrict__ xo, int total4) {
    int i = blockIdx.x * blockDim.x + threadIdx.x;
    if (i < total4) {
        float4 v = *(const float4*)(x + i * 4);
        __half2 a = __floats2half2_rn(v.x, v.y);
        __half2 b = __floats2half2_rn(v.z, v.w);
        *(uint2*)(xo + i * 4) = make_uint2(*(unsigned*)&a, *(unsigned*)&b);
    }
}

// ---------------- fp16 tensor-core GEMM: Hout = fp16(dinv * (X @ W)) ------
#define XS_H 136
#define BS_W 132

__device__ __forceinline__ void mma_f16(float* d,
                                        unsigned a0, unsigned a1, unsigned a2, unsigned a3,
                                        unsigned b0, unsigned b1) {
    asm volatile("mma.sync.aligned.m16n8k16.row.col.f32.f16.f16.f32 "
                 "{%0,%1,%2,%3}, {%4,%5,%6,%7}, {%8,%9}, {%0,%1,%2,%3};"
                 : "+f"(d[0]), "+f"(d[1]), "+f"(d[2]), "+f"(d[3])
                 : "r"(a0), "r"(a1), "r"(a2), "r"(a3), "r"(b0), "r"(b1));
}

__global__ __launch_bounds__(256) void gemm_f16_k(const __half* __restrict__ X,
                                                  const float* __restrict__ W,
                                                  __half* __restrict__ Hout, int n) {
    extern __shared__ char shraw[];
    __half*  xs = (__half*)shraw;                    // 64 x XS_H halfs
    __half2* bs = (__half2*)(shraw + 64 * XS_H * 2); // 64 x BS_W half2 (k-pairs)

    int t = threadIdx.x;
    int row0 = blockIdx.x * 64;
    int nr = n - row0; if (nr > 64) nr = 64;

    for (int i = t; i < 64 * 128; i += 256) {
        int k2 = i >> 7, nn = i & 127;
        float w0 = W[(size_t)(2 * k2) * 128 + nn];
        float w1 = W[(size_t)(2 * k2 + 1) * 128 + nn];
        bs[k2 * BS_W + nn] = __floats2half2_rn(w0, w1);
    }
    for (int i = t; i < nr * 16; i += 256) {
        int rr = i >> 4, c8 = i & 15;
        uint4 v = *(const uint4*)(X + (size_t)(row0 + rr) * 128 + c8 * 8);
        *(uint4*)(xs + rr * XS_H + c8 * 8) = v;
    }
    __syncthreads();

    int lane = t & 31, wid = t >> 5;
    int wm = wid & 1, wn = wid >> 1;
    int m0 = wm * 32, n0 = wn * 32;
    int r = lane >> 2, c = lane & 3;

    float acc[2][4][4];
#pragma unroll
    for (int mi = 0; mi < 2; mi++)
#pragma unroll
        for (int nj = 0; nj < 4; nj++)
#pragma unroll
            for (int q = 0; q < 4; q++) acc[mi][nj][q] = 0.f;

#pragma unroll
    for (int k0 = 0; k0 < 8; k0++) {
        unsigned a[2][4];
#pragma unroll
        for (int mi = 0; mi < 2; mi++) {
            const __half* xb = xs + (m0 + mi * 16 + r) * XS_H + k0 * 16 + 2 * c;
            a[mi][0] = *(const unsigned*)(xb);
            a[mi][1] = *(const unsigned*)(xb + 8 * XS_H);
            a[mi][2] = *(const unsigned*)(xb + 8);
            a[mi][3] = *(const unsigned*)(xb + 8 * XS_H + 8);
        }
#pragma unroll
        for (int nj = 0; nj < 4; nj++) {
            const __half2* bb = bs + (k0 * 8 + c) * BS_W + n0 + nj * 8 + r;
            unsigned b0 = *(const unsigned*)(bb);
            unsigned b1 = *(const unsigned*)(bb + 4 * BS_W);
#pragma unroll
            for (int mi = 0; mi < 2; mi++)
                mma_f16(acc[mi][nj], a[mi][0], a[mi][1], a[mi][2], a[mi][3], b0, b1);
        }
    }

#pragma unroll
    for (int mi = 0; mi < 2; mi++) {
        int rloc = m0 + mi * 16 + r;
        float s0 = 0.f, s1 = 0.f;
        if (rloc < nr)     s0 = d_dinv[row0 + rloc];
        if (rloc + 8 < nr) s1 = d_dinv[row0 + rloc + 8];
#pragma unroll
        for (int nj = 0; nj < 4; nj++) {
            int col = n0 + nj * 8 + 2 * c;
            if (rloc < nr) {
                __half2 h = __floats2half2_rn(acc[mi][nj][0] * s0, acc[mi][nj][1] * s0);
                *(__half2*)(Hout + (size_t)(row0 + rloc) * 128 + col) = h;
            }
            if (rloc + 8 < nr) {
                __half2 h = __floats2half2_rn(acc[mi][nj][2] * s1, acc[mi][nj][3] * s1);
                *(__half2*)(Hout + (size_t)(row0 + rloc + 8) * 128 + col) = h;
            }
        }
    }
}

// ---------------- aggregation: half-warp per node, segment-masked shuffles -
// out_i = fp16( relu(dinv_i * (sum_{e:dst=i} H'[src] + H'[i]) + b) )
__global__ __launch_bounds__(256) void aggregate_k(const __half* __restrict__ H,
                                                   const float* __restrict__ bias,
                                                   __half* __restrict__ outp, int n,
                                                   int dopool) {
    __shared__ float pS[16][128];
    __shared__ float pM[16][128];
    int t = threadIdx.x;
    int hw = t >> 4;          // half-warp id in block, 0..15
    int lane16 = t & 15;
    int w = blockIdx.x * 16 + hw;
    // segment mask: lanes of THIS half-warp only (same w -> convergent loop)
    unsigned hmask = 0xFFFFu << (t & 16);

    float o[8];
#pragma unroll
    for (int q = 0; q < 8; q++) o[q] = 0.f;

    if (w < n) {
        float acc[8];
#pragma unroll
        for (int q = 0; q < 8; q++) acc[q] = 0.f;
        int beg = d_rowstart[w];
        int end = d_rowstart[w + 1];
        const __half* Hl = H + lane16 * 8;
        for (int base = beg; base < end; base += 16) {
            int rem = end - base;
            int cnt = rem < 16 ? rem : 16;
            int idx = (lane16 < cnt) ? d_csr[base + lane16] : 0;
            uint4 h[4];
            int m0 = cnt < 4 ? cnt : 4;
#pragma unroll
            for (int u = 0; u < 4; u++) {
                if (u < m0) {
                    int s = __shfl_sync(hmask, idx, u, 16);
                    h[u] = *(const uint4*)(Hl + (size_t)s * 128);
                }
            }
            for (int j0 = 0; j0 < cnt; j0 += 4) {
                int curm = cnt - j0; if (curm > 4) curm = 4;
                int nxtm = cnt - j0 - 4;
                if (nxtm < 0) nxtm = 0;
                if (nxtm > 4) nxtm = 4;
                uint4 h2[4];
#pragma unroll
                for (int u = 0; u < 4; u++) {
                    if (u < nxtm) {
                        int s = __shfl_sync(hmask, idx, j0 + 4 + u, 16);
                        h2[u] = *(const uint4*)(Hl + (size_t)s * 128);
                    } else {
                        h2[u] = make_uint4(0u, 0u, 0u, 0u);
                    }
                }
#pragma unroll
                for (int u = 0; u < 4; u++) {
                    if (u < curm) {
                        const __half2* p2 = (const __half2*)&h[u];
#pragma unroll
                        for (int q = 0; q < 4; q++) {
                            float2 f = __half22float2(p2[q]);
                            acc[2 * q]     += f.x;
                            acc[2 * q + 1] += f.y;
                        }
                    }
                }
#pragma unroll
                for (int u = 0; u < 4; u++) h[u] = h2[u];
            }
        }
        // self-loop
        {
            uint4 hs = *(const uint4*)(Hl + (size_t)w * 128);
            const __half2* p2 = (const __half2*)&hs;
#pragma unroll
            for (int q = 0; q < 4; q++) {
                float2 f = __half22float2(p2[q]);
                acc[2 * q]     += f.x;
                acc[2 * q + 1] += f.y;
            }
        }
        float di = d_dinv[w];
        float4 b0 = *(const float4*)(bias + lane16 * 8);
        float4 b1 = *(const float4*)(bias + lane16 * 8 + 4);
        o[0] = fmaxf(di * acc[0] + b0.x, 0.f);
        o[1] = fmaxf(di * acc[1] + b0.y, 0.f);
        o[2] = fmaxf(di * acc[2] + b0.z, 0.f);
        o[3] = fmaxf(di * acc[3] + b0.w, 0.f);
        o[4] = fmaxf(di * acc[4] + b1.x, 0.f);
        o[5] = fmaxf(di * acc[5] + b1.y, 0.f);
        o[6] = fmaxf(di * acc[6] + b1.z, 0.f);
        o[7] = fmaxf(di * acc[7] + b1.w, 0.f);
        __half2 ho[4];
#pragma unroll
        for (int q = 0; q < 4; q++) ho[q] = __floats2half2_rn(o[2 * q], o[2 * q + 1]);
        *(uint4*)(outp + (size_t)w * 128 + lane16 * 8) = *(uint4*)ho;
    }

    if (dopool) {
#pragma unroll
        for (int q = 0; q < 8; q++) {
            pS[hw][lane16 * 8 + q] = o[q];
            pM[hw][lane16 * 8 + q] = o[q];
        }
        __syncthreads();
        if (t < 128) {
            float s = 0.f, mx = 0.f;
#pragma unroll
            for (int u = 0; u < 16; u++) { s += pS[u][t]; mx = fmaxf(mx, pM[u][t]); }
            atomicAdd(&d_scr.poolsum[t], s);
            atomicMax(&d_scr.poolmax[t], __float_as_uint(mx));
        }
    }
}

// ---------------- argmax key helpers ----------------
__device__ __forceinline__ unsigned enc_f(float f) {
    unsigned u = __float_as_uint(f);
    return (u & 0x80000000u) ? ~u : (u | 0x80000000u);
}
__device__ __forceinline__ unsigned long long mkkey(float f, int j) {
    return ((unsigned long long)enc_f(f) << 32) | (unsigned long long)(0xFFFFFFFFu - (unsigned)j);
}

// ---------------- head GEMVs + inline pool final + z1 block stats ----------
__global__ __launch_bounds__(256) void gemv_heads_k(const float* __restrict__ n1W,
                                                    const float* __restrict__ n1b,
                                                    const float* __restrict__ g1,
                                                    const float* __restrict__ n2W,
                                                    const float* __restrict__ n2b,
                                                    int ncols, int halfblocks, float inv_n) {
    __shared__ float p[256];
    __shared__ float red[256];
    __shared__ unsigned long long redk[256];
    int t = threadIdx.x;
    if (t < 128) p[t] = d_scr.poolsum[t] * inv_n;
    else         p[t] = __uint_as_float(d_scr.poolmax[t - 128]);
    __syncthreads();
    int second = blockIdx.x >= halfblocks;
    int b = second ? blockIdx.x - halfblocks : blockIdx.x;
    int j4 = b * blockDim.x + t;
    bool valid = (j4 * 4 < ncols);
    float ax = 0.f, ay = 0.f, az = 0.f, aw = 0.f;
    if (valid) {
        const float* W = second ? n2W : n1W;
#pragma unroll 4
        for (int k = 0; k < 256; k++) {
            float4 w4 = *(const float4*)(W + (size_t)k * ncols + j4 * 4);
            float pv = p[k];
            ax += pv * w4.x; ay += pv * w4.y; az += pv * w4.z; aw += pv * w4.w;
        }
    }
    int j = j4 * 4;
    if (!second) {
        float4 o = make_float4(0.f, 0.f, 0.f, 0.f);
        if (valid) {
            float4 bb = *(const float4*)(n1b + j);
            float4 gg = *(const float4*)(g1 + j);
            o.x = (ax + bb.x + gg.x) * INV_TAU;
            o.y = (ay + bb.y + gg.y) * INV_TAU;
            o.z = (az + bb.z + gg.z) * INV_TAU;
            o.w = (aw + bb.w + gg.w) * INV_TAU;
            *(float4*)(d_z1 + j) = o;
        }
        float lm = valid ? fmaxf(fmaxf(o.x, o.y), fmaxf(o.z, o.w)) : -1e30f;
        red[t] = lm;
        __syncthreads();
        for (int s = 128; s > 0; s >>= 1) {
            if (t < s) red[t] = fmaxf(red[t], red[t + s]);
            __syncthreads();
        }
        float bm = red[0];
        __syncthreads();
        float ls = 0.f;
        if (valid) {
            ls = expf(o.x - bm) + expf(o.y - bm) + expf(o.z - bm) + expf(o.w - bm);
        }
        red[t] = ls;
        unsigned long long key = 0ull;
        if (valid) {
            key = mkkey(o.x, j);
            unsigned long long k1 = mkkey(o.y, j + 1); if (k1 > key) key = k1;
            unsigned long long k2 = mkkey(o.z, j + 2); if (k2 > key) key = k2;
            unsigned long long k3 = mkkey(o.w, j + 3); if (k3 > key) key = k3;
        }
        redk[t] = key;
        __syncthreads();
        for (int s = 128; s > 0; s >>= 1) {
            if (t < s) {
                red[t] += red[t + s];
                if (redk[t + s] > redk[t]) redk[t] = redk[t + s];
            }
            __syncthreads();
        }
        if (t == 0) {
            d_bm[0][b] = bm;
            d_bs[0][b] = red[0];
            d_bk[0][b] = redk[0];
        }
    } else {
        if (valid) {
            float4 bb = *(const float4*)(n2b + j);
            float4 o;
            o.x = ax + bb.x; o.y = ay + bb.y; o.z = az + bb.z; o.w = aw + bb.w;
            *(float4*)(d_l2 + j) = o;
        }
    }
}

// ---------------- merge block stats -> global M, S, argmax ----------------
__global__ void merge_k(int which, int nb) {
    __shared__ float sm[128];
    __shared__ float ss[128];
    __shared__ unsigned long long sk[128];
    int t = threadIdx.x;  // 128
    float m = (t < nb) ? d_bm[which][t] : -1e30f;
    sm[t] = m;
    __syncthreads();
    for (int s = 64; s > 0; s >>= 1) {
        if (t < s) sm[t] = fmaxf(sm[t], sm[t + s]);
        __syncthreads();
    }
    float M = sm[0];
    __syncthreads();
    float ls = (t < nb) ? d_bs[which][t] * expf(d_bm[which][t] - M) : 0.f;
    ss[t] = ls;
    sk[t] = (t < nb) ? d_bk[which][t] : 0ull;
    __syncthreads();
    for (int s = 64; s > 0; s >>= 1) {
        if (t < s) {
            ss[t] += ss[t + s];
            if (sk[t + s] > sk[t]) sk[t] = sk[t + s];
        }
        __syncthreads();
    }
    if (t == 0) {
        d_scr.zmax[which] = M;
        d_scr.S[which] = ss[0];
        int idx = (int)(0xFFFFFFFFu - (unsigned)(sk[0] & 0xFFFFFFFFull));
        d_scr.isel[which] = idx;
        if (which == 0) d_conn[idx] = 1;
    }
}

// ---------------- mask of nodes connected to i1 ----------------
__global__ void conn_k(const int* __restrict__ srcp, const int* __restrict__ dstp, int E) {
    int i1 = d_scr.isel[0];
    int e = blockIdx.x * blockDim.x + threadIdx.x;
    if (e < E) {
        int s = srcp[e], d = dstp[e];
        if (s == i1 || d == i1) { d_conn[s] = 1; d_conn[d] = 1; }
    }
}

// ---------------- fused A: [write n1_soft] || [z2 compute + block stats] ----
__global__ __launch_bounds__(256) void fused_a_k(const float* __restrict__ g2,
                                                 float* __restrict__ outp, int n, int WB) {
    __shared__ float red[256];
    __shared__ unsigned long long redk[256];
    int t = threadIdx.x;
    if ((int)blockIdx.x < WB) {
        float M = d_scr.zmax[0];
        float invS = 1.0f / d_scr.S[0];
        int j4 = blockIdx.x * 256 + t;
        int j = j4 * 4;
        if (j < n) {
            float4 z = *(const float4*)(d_z1 + j);
            float4 o;
            o.x = expf(z.x - M) * invS;
            o.y = expf(z.y - M) * invS;
            o.z = expf(z.z - M) * invS;
            o.w = expf(z.w - M) * invS;
            *(float4*)(outp + j) = o;
        }
        return;
    }
    int b = blockIdx.x - WB;
    int j4 = b * 256 + t;
    int j = j4 * 4;
    bool valid = (j < n);
    float4 z = make_float4(0.f, 0.f, 0.f, 0.f);
    if (valid) {
        float4 l = *(const float4*)(d_l2 + j);
        uchar4 cn = *(const uchar4*)(d_conn + j);
        float4 g = *(const float4*)(g2 + j);
        z.x = ((cn.x ? MASKV : l.x) + g.x) * INV_TAU;
        z.y = ((cn.y ? MASKV : l.y) + g.y) * INV_TAU;
        z.z = ((cn.z ? MASKV : l.z) + g.z) * INV_TAU;
        z.w = ((cn.w ? MASKV : l.w) + g.w) * INV_TAU;
        *(float4*)(d_z2 + j) = z;
    }
    float lm = valid ? fmaxf(fmaxf(z.x, z.y), fmaxf(z.z, z.w)) : -1e30f;
    red[t] = lm;
    __syncthreads();
    for (int s = 128; s > 0; s >>= 1) {
        if (t < s) red[t] = fmaxf(red[t], red[t + s]);
        __syncthreads();
    }
    float bm = red[0];
    __syncthreads();
    float ls = 0.f;
    if (valid) ls = expf(z.x - bm) + expf(z.y - bm) + expf(z.z - bm) + expf(z.w - bm);
    red[t] = ls;
    unsigned long long key = 0ull;
    if (valid) {
        key = mkkey(z.x, j);
        unsigned long long k1 = mkkey(z.y, j + 1); if (k1 > key) key = k1;
        unsigned long long k2 = mkkey(z.z, j + 2); if (k2 > key) key = k2;
        unsigned long long k3 = mkkey(z.w, j + 3); if (k3 > key) key = k3;
    }
    redk[t] = key;
    __syncthreads();
    for (int s = 128; s > 0; s >>= 1) {
        if (t < s) {
            red[t] += red[t + s];
            if (redk[t + s] > redk[t]) redk[t] = redk[t + s];
        }
        __syncthreads();
    }
    if (t == 0) {
        d_bm[1][b] = bm;
        d_bs[1][b] = red[0];
        d_bk[1][b] = redk[0];
    }
}

// ---------------- fused B: [esoft] || [write n2_soft] ----------------
__global__ __launch_bounds__(256) void fused_b_k(const __half* __restrict__ G,
                                                 const float* __restrict__ eW,
                                                 const float* __restrict__ eb,
                                                 const float* __restrict__ ge,
                                                 float* __restrict__ outp, int n) {
    int t = threadIdx.x;
    if (blockIdx.x == 0) {
        __shared__ float red3[3][128];
        int i1 = d_scr.isel[0];
        int i2 = d_scr.isel[1];
        if (t < 128) {
            float a = __half2float(G[(size_t)i1 * 128 + t]);
            float b = __half2float(G[(size_t)i2 * 128 + t]);
#pragma unroll
            for (int o = 0; o < 3; o++)
                red3[o][t] = a * eW[t * 3 + o] + b * eW[(128 + t) * 3 + o];
        }
        __syncthreads();
        for (int s = 64; s > 0; s >>= 1) {
            if (t < s) {
                red3[0][t] += red3[0][t + s];
                red3[1][t] += red3[1][t + s];
                red3[2][t] += red3[2][t + s];
            }
            __syncthreads();
        }
        if (t == 0) {
            float z0 = (red3[0][0] + eb[0] + ge[0]) * INV_TAU;
            float z1v = (red3[1][0] + eb[1] + ge[1]) * INV_TAU;
            float z2v = (red3[2][0] + eb[2] + ge[2]) * INV_TAU;
            float m = fmaxf(z0, fmaxf(z1v, z2v));
            float e0 = expf(z0 - m), e1 = expf(z1v - m), e2 = expf(z2v - m);
            float inv = 1.0f / (e0 + e1 + e2);
            outp[2 * n + 0] = e0 * inv;
            outp[2 * n + 1] = e1 * inv;
            outp[2 * n + 2] = e2 * inv;
            outp[2 * n + 3] = 1.0f;
        }
        return;
    }
    float M = d_scr.zmax[1];
    float invS = 1.0f / d_scr.S[1];
    int j4 = (blockIdx.x - 1) * 256 + t;
    int j = j4 * 4;
    if (j < n) {
        float4 z = *(const float4*)(d_z2 + j);
        float4 o;
        o.x = expf(z.x - M) * invS;
        o.y = expf(z.y - M) * invS;
        o.z = expf(z.z - M) * invS;
        o.w = expf(z.w - M) * invS;
        *(float4*)(outp + n + j) = o;
    }
}

// ---------------- launcher (single stream — graph-capture safe) ----------
extern "C" void kernel_launch(void* const* d_in, const int* in_sizes, int n_in,
                              void* d_out, int out_size) {
    const float* x   = (const float*)d_in[0];
    const int*   ei  = (const int*)  d_in[1];
    const float* W1  = (const float*)d_in[2];
    const float* b1  = (const float*)d_in[3];
    const float* W2  = (const float*)d_in[4];
    const float* b2  = (const float*)d_in[5];
    const float* W3  = (const float*)d_in[6];
    const float* b3  = (const float*)d_in[7];
    const float* n1W = (const float*)d_in[8];
    const float* n1b = (const float*)d_in[9];
    const float* n2W = (const float*)d_in[10];
    const float* n2b = (const float*)d_in[11];
    const float* eW  = (const float*)d_in[12];
    const float* eb  = (const float*)d_in[13];
    const float* g1  = (const float*)d_in[16];
    const float* g2  = (const float*)d_in[17];
    const float* ge  = (const float*)d_in[18];
    float* out = (float*)d_out;

    int n = in_sizes[0] / 128;
    int E = in_sizes[1] / 2;
    const int* srcp = ei;
    const int* dstp = ei + E;

    void *pc, *pconn, *pscr, *pH, *pP, *pQ;
    cudaGetSymbolAddress(&pc,    d_counts);
    cudaGetSymbolAddress(&pconn, d_conn);
    cudaGetSymbolAddress(&pscr,  d_scr);
    cudaGetSymbolAddress(&pH,    d_H);
    cudaGetSymbolAddress(&pP,    d_P);
    cudaGetSymbolAddress(&pQ,    d_Q);
    __half* H = (__half*)pH;
    __half* P = (__half*)pP;
    __half* Q = (__half*)pQ;

    const int GEMM_SMEM = 64 * XS_H * 2 + 64 * BS_W * 4;  // 51200 B
    cudaFuncSetAttribute(gemm_f16_k, cudaFuncAttributeMaxDynamicSharedMemorySize, GEMM_SMEM);

    cudaMemsetAsync(pc,    0, (size_t)n * sizeof(int), 0);
    cudaMemsetAsync(pconn, 0, (size_t)n, 0);
    cudaMemsetAsync(pscr,  0, sizeof(Scr), 0);

    int eblocks = (E + 255) / 256;
    int nb = (n + 1023) / 1024;
    degcount_k<<<eblocks, 256>>>(dstp, E);
    scan1_k<<<nb, 1024>>>(n);
    scan2_k<<<1, 128>>>(nb, n);
    scan3_k<<<nb, 1024>>>(n);
    fill_csr_k<<<eblocks, 256>>>(srcp, dstp, E);

    int total4 = n * 32;
    cvt_x_k<<<(total4 + 255) / 256, 256>>>(x, P, total4);

    int gblocks = (n + 63) / 64;
    int ablocks = (n + 15) / 16;        // half-warp per node

    gemm_f16_k<<<gblocks, 256, GEMM_SMEM>>>(P, W1, H, n);
    aggregate_k<<<ablocks, 256>>>(H, b1, Q, n, 0);
    gemm_f16_k<<<gblocks, 256, GEMM_SMEM>>>(Q, W2, H, n);
    aggregate_k<<<ablocks, 256>>>(H, b2, P, n, 0);
    gemm_f16_k<<<gblocks, 256, GEMM_SMEM>>>(P, W3, H, n);
    aggregate_k<<<ablocks, 256>>>(H, b3, Q, n, 1);  // Q = gcn, pool fused

    int halfblocks = (n / 4 + 255) / 256;       // 98
    gemv_heads_k<<<2 * halfblocks, 256>>>(n1W, n1b, g1, n2W, n2b, n, halfblocks,
                                          1.0f / (float)n);
    merge_k<<<1, 128>>>(0, halfblocks);
    conn_k<<<eblocks, 256>>>(srcp, dstp, E);

    int WB = (n + 1023) / 1024;                  // 98
    fused_a_k<<<2 * WB, 256>>>(g2, out, n, WB);
    merge_k<<<1, 128>>>(1, WB);
    fused_b_k<<<WB + 1, 256>>>(Q, eW, eb, ge, out, n);
}